// round 8
// baseline (speedup 1.0000x reference)
#include <cuda_runtime.h>
#include <cuda_fp16.h>
#include <cstdint>
#include <math.h>

// Problem dims
#define Bv   32
#define Sv   128
#define Hv   768
#define Lv   12
#define NHv  12
#define DHv  64
#define FFv  3072
#define Tv   10
#define Cv   16
#define CLSv 101

#define NTOK (Bv*Sv)          // 4096

// ---------------- scratch (device globals; no allocation allowed) ----------
__device__ __align__(16) float g_x  [NTOK*Hv];
__device__ __align__(16) float g_q  [NTOK*Hv];
__device__ __align__(16) float g_k  [NTOK*Hv];
__device__ __align__(16) float g_v  [NTOK*Hv];
__device__ __align__(16) float g_ctx[NTOK*Hv];
__device__ __align__(16) float g_t1 [NTOK*Hv];
__device__ __align__(16) float g_ff [NTOK*FFv];
__device__ __align__(16) float g_xt [Bv*Hv];
__device__ __align__(16) float g_h  [Bv*Hv];
__device__ __align__(16) float g_gi [Bv*3*Hv];
__device__ __align__(16) float g_gh [Bv*3*Hv];

// =================== FP16 tensor-core GEMM (m16n8k16) =======================
// C[M,N] = A[M,K] @ B[K,N] + bias (EPI=1: + exact GELU), fp32 accumulate.
// Inputs converted fp32->fp16 (RN) on the SMEM-store path; same 10-bit
// mantissa as TF32. Requires M%128==0, N%64==0, K%32==0.
// gridDim.z selects among 3 (B, bias, C) triples (QKV fusion).
//
// Block tile 128x64, 8 warps, warp tile 32x32, K-chunk 32 (2 k16 steps).
// SMEM (words): As[128][20] (32 halfs data + 8 pad), Bs[32][36] (64 halfs + 8 pad).
// A-frag reads bank-clean (20r+off); B via ldmatrix.x4.trans (rows 4k: clean).
// Structure per R4 (best known): prefetch -> compute -> sync -> store -> sync.

#define LDA_H 20
#define LDB_H 36

__device__ __forceinline__ uint32_t packh2(float lo, float hi) {
    __half2 h = __floats2half2_rn(lo, hi);   // lo -> .x (low half)
    return *reinterpret_cast<uint32_t*>(&h);
}

__device__ __forceinline__ void mma_f16(float c[4],
    uint32_t a0, uint32_t a1, uint32_t a2, uint32_t a3,
    uint32_t b0, uint32_t b1)
{
    asm volatile(
        "mma.sync.aligned.m16n8k16.row.col.f32.f16.f16.f32 "
        "{%0,%1,%2,%3}, {%4,%5,%6,%7}, {%8,%9}, {%0,%1,%2,%3};"
        : "+f"(c[0]), "+f"(c[1]), "+f"(c[2]), "+f"(c[3])
        : "r"(a0), "r"(a1), "r"(a2), "r"(a3), "r"(b0), "r"(b1));
}

__device__ __forceinline__ void ldsm4t(uint32_t& r0, uint32_t& r1,
                                       uint32_t& r2, uint32_t& r3, uint32_t addr)
{
    asm volatile("ldmatrix.sync.aligned.m8n8.x4.trans.shared.b16 {%0,%1,%2,%3}, [%4];"
        : "=r"(r0), "=r"(r1), "=r"(r2), "=r"(r3) : "r"(addr));
}

template<int EPI>
__global__ __launch_bounds__(256, 2) void gemm_f16_kernel(
    const float* __restrict__ A,
    const float* __restrict__ B0, const float* __restrict__ B1, const float* __restrict__ B2,
    const float* __restrict__ bias0, const float* __restrict__ bias1, const float* __restrict__ bias2,
    float* __restrict__ C0, float* __restrict__ C1, float* __restrict__ C2,
    int M, int N, int K)
{
    const int z = blockIdx.z;
    const float* B    = (z == 0) ? B0    : (z == 1) ? B1    : B2;
    const float* bias = (z == 0) ? bias0 : (z == 1) ? bias1 : bias2;
    float*       C    = (z == 0) ? C0    : (z == 1) ? C1    : C2;

    __shared__ uint32_t As[128 * LDA_H];   // 10 KB
    __shared__ uint32_t Bs[32 * LDB_H];    // 4.5 KB

    const int tid  = threadIdx.x;
    const int bm   = blockIdx.y * 128;
    const int bn   = blockIdx.x * 64;
    const int w    = tid >> 5, lane = tid & 31;
    const int warpM = w & 3;            // rows warpM*32
    const int warpN = w >> 2;           // cols warpN*32
    const int r    = lane >> 2;         // 0..7
    const int off  = lane & 3;          // 0..3

    // writer assignments (same global-coalesced pattern as R4)
    const int amrow = tid >> 3, ac = tid & 7;     // A rows amrow+32i, k-halfs 4ac..+3
    const int bkrow = tid >> 4, be = tid & 15;    // B k-rows bkrow+16i, n-halfs 4be..+3

    const float* Abase = A + (size_t)bm * K;
    const float* Bbase = B + bn;

    // A-frag reader base (word units)
    const int aBase = (warpM * 32 + r) * LDA_H + off;
    // B ldmatrix per-thread base byte address:
    //   row k = lane&15, col halfs = warpN*32 + ((lane>>4)&1)*8
    const uint32_t bs0 = (uint32_t)__cvta_generic_to_shared(Bs);
    const uint32_t ldsmBase = bs0 +
        (uint32_t)(((lane & 15) * LDB_H + warpN * 16 + ((lane >> 4) & 1) * 4) * 4);

    float4 ra[4], rb[2];

    // ---- prologue: load chunk 0, store ----
    #pragma unroll
    for (int i = 0; i < 4; i++)
        ra[i] = *(const float4*)(Abase + (size_t)(amrow + i * 32) * K + ac * 4);
    #pragma unroll
    for (int i = 0; i < 2; i++)
        rb[i] = *(const float4*)(Bbase + (size_t)(bkrow + i * 16) * N + be * 4);

    #pragma unroll
    for (int i = 0; i < 4; i++) {
        int m = amrow + i * 32;
        *(uint2*)&As[m * LDA_H + 2 * ac] =
            make_uint2(packh2(ra[i].x, ra[i].y), packh2(ra[i].z, ra[i].w));
    }
    #pragma unroll
    for (int i = 0; i < 2; i++) {
        int k = bkrow + i * 16;
        *(uint2*)&Bs[k * LDB_H + 2 * be] =
            make_uint2(packh2(rb[i].x, rb[i].y), packh2(rb[i].z, rb[i].w));
    }
    __syncthreads();

    float acc[2][4][4] = {};
    const int nk = K >> 5;

    #pragma unroll 1
    for (int ch = 0; ch < nk; ch++) {
        const bool has_next = (ch + 1) < nk;
        if (has_next) {
            int kk = (ch + 1) * 32;
            #pragma unroll
            for (int i = 0; i < 4; i++)
                ra[i] = *(const float4*)(Abase + (size_t)(amrow + i * 32) * K + kk + ac * 4);
            #pragma unroll
            for (int i = 0; i < 2; i++)
                rb[i] = *(const float4*)(Bbase + (size_t)(kk + bkrow + i * 16) * N + be * 4);
        }

        #pragma unroll
        for (int ks = 0; ks < 2; ks++) {
            // B fragments: two ldmatrix.x4.trans cover nt=0..3
            uint32_t bf[4][2];
            uint32_t baddr = ldsmBase + (uint32_t)(ks * 16 * LDB_H * 4);
            ldsm4t(bf[0][0], bf[0][1], bf[1][0], bf[1][1], baddr);
            ldsm4t(bf[2][0], bf[2][1], bf[3][0], bf[3][1], baddr + 32);

            // A fragments: 4 LDS.32 each, bank-clean, immediate offsets
            uint32_t af[2][4];
            #pragma unroll
            for (int mt = 0; mt < 2; mt++) {
                int b0i = aBase + mt * (16 * LDA_H) + ks * 8;
                af[mt][0] = As[b0i];
                af[mt][1] = As[b0i + 8 * LDA_H];
                af[mt][2] = As[b0i + 4];
                af[mt][3] = As[b0i + 8 * LDA_H + 4];
            }
            #pragma unroll
            for (int mt = 0; mt < 2; mt++)
                #pragma unroll
                for (int nt = 0; nt < 4; nt++)
                    mma_f16(acc[mt][nt], af[mt][0], af[mt][1], af[mt][2], af[mt][3],
                            bf[nt][0], bf[nt][1]);
        }
        __syncthreads();

        if (has_next) {
            #pragma unroll
            for (int i = 0; i < 4; i++) {
                int m = amrow + i * 32;
                *(uint2*)&As[m * LDA_H + 2 * ac] =
                    make_uint2(packh2(ra[i].x, ra[i].y), packh2(ra[i].z, ra[i].w));
            }
            #pragma unroll
            for (int i = 0; i < 2; i++) {
                int k = bkrow + i * 16;
                *(uint2*)&Bs[k * LDB_H + 2 * be] =
                    make_uint2(packh2(rb[i].x, rb[i].y), packh2(rb[i].z, rb[i].w));
            }
            __syncthreads();
        }
    }

    // epilogue (same fragment->C mapping as k8 path)
    #pragma unroll
    for (int mt = 0; mt < 2; mt++) {
        #pragma unroll
        for (int nt = 0; nt < 4; nt++) {
            int row0 = bm + warpM * 32 + mt * 16 + r;
            int col  = bn + warpN * 32 + nt * 8 + off * 2;
            float b0 = bias[col], b1 = bias[col + 1];
            float v00 = acc[mt][nt][0] + b0;
            float v01 = acc[mt][nt][1] + b1;
            float v10 = acc[mt][nt][2] + b0;
            float v11 = acc[mt][nt][3] + b1;
            if (EPI == 1) {
                v00 = 0.5f * v00 * (1.0f + erff(v00 * 0.70710678118654752f));
                v01 = 0.5f * v01 * (1.0f + erff(v01 * 0.70710678118654752f));
                v10 = 0.5f * v10 * (1.0f + erff(v10 * 0.70710678118654752f));
                v11 = 0.5f * v11 * (1.0f + erff(v11 * 0.70710678118654752f));
            }
            *(float2*)(C + (size_t)row0 * N + col)       = make_float2(v00, v01);
            *(float2*)(C + (size_t)(row0 + 8) * N + col) = make_float2(v10, v11);
        }
    }
}

static inline dim3 tc_grid(int M, int N, int z = 1) { return dim3(N / 64, M / 128, z); }

// =================== FFMA GEMM (small / decoder shapes) =====================
template<bool TRANSB, int EPI>
__global__ __launch_bounds__(256) void gemm_kernel(
    const float* __restrict__ A, const float* __restrict__ B,
    const float* __restrict__ bias, float* __restrict__ C,
    int M, int N, int K, int ldc)
{
    __shared__ float As[16][64];
    __shared__ float Bs[16][64];
    const int tid = threadIdx.x;
    const int bm = blockIdx.y * 64, bn = blockIdx.x * 64;
    const int ty = tid >> 4, tx = tid & 15;

    const int lm  = tid >> 2;
    const int lk4 = (tid & 3) * 4;
    const int lbk = tid >> 4;
    const int lbn4 = (tid & 15) * 4;

    float acc[4][4] = {};

    for (int kk = 0; kk < K; kk += 16) {
        float4 av = make_float4(0.f,0.f,0.f,0.f);
        if (bm + lm < M)
            av = *(const float4*)(A + (size_t)(bm + lm) * K + kk + lk4);
        As[lk4+0][lm] = av.x; As[lk4+1][lm] = av.y;
        As[lk4+2][lm] = av.z; As[lk4+3][lm] = av.w;

        if (TRANSB) {
            float4 bvv = make_float4(0.f,0.f,0.f,0.f);
            if (bn + lm < N)
                bvv = *(const float4*)(B + (size_t)(bn + lm) * K + kk + lk4);
            Bs[lk4+0][lm] = bvv.x; Bs[lk4+1][lm] = bvv.y;
            Bs[lk4+2][lm] = bvv.z; Bs[lk4+3][lm] = bvv.w;
        } else {
            float4 bvv = make_float4(0.f,0.f,0.f,0.f);
            if (bn + lbn4 < N)
                bvv = *(const float4*)(B + (size_t)(kk + lbk) * N + bn + lbn4);
            *(float4*)&Bs[lbk][lbn4] = bvv;
        }
        __syncthreads();

        #pragma unroll
        for (int k = 0; k < 16; k++) {
            float4 a = *(const float4*)&As[k][ty * 4];
            float4 b = *(const float4*)&Bs[k][tx * 4];
            acc[0][0] += a.x*b.x; acc[0][1] += a.x*b.y; acc[0][2] += a.x*b.z; acc[0][3] += a.x*b.w;
            acc[1][0] += a.y*b.x; acc[1][1] += a.y*b.y; acc[1][2] += a.y*b.z; acc[1][3] += a.y*b.w;
            acc[2][0] += a.z*b.x; acc[2][1] += a.z*b.y; acc[2][2] += a.z*b.z; acc[2][3] += a.z*b.w;
            acc[3][0] += a.w*b.x; acc[3][1] += a.w*b.y; acc[3][2] += a.w*b.z; acc[3][3] += a.w*b.w;
        }
        __syncthreads();
    }

    #pragma unroll
    for (int i = 0; i < 4; i++) {
        int row = bm + ty * 4 + i;
        if (row >= M) continue;
        #pragma unroll
        for (int j = 0; j < 4; j++) {
            int col = bn + tx * 4 + j;
            if (col >= N) continue;
            float vv = acc[i][j] + bias[col];
            if (EPI == 1) vv = 0.5f * vv * (1.0f + erff(vv * 0.70710678118654752f));
            C[(size_t)row * ldc + col] = vv;
        }
    }
}

static inline dim3 gemm_grid(int M, int N) { return dim3((N + 63) / 64, (M + 63) / 64); }

// ---------------- LayerNorm helpers ----------------------------------------
__device__ __forceinline__ float block_sum256(float v, float* red) {
    int tid = threadIdx.x;
    red[tid] = v;
    __syncthreads();
    #pragma unroll
    for (int s = 128; s > 0; s >>= 1) {
        if (tid < s) red[tid] += red[tid + s];
        __syncthreads();
    }
    float r = red[0];
    __syncthreads();
    return r;
}

__global__ __launch_bounds__(256) void embed_ln_kernel(
    const int* __restrict__ ids, const float* __restrict__ ew,
    const float* __restrict__ ep, const float* __restrict__ et,
    const float* __restrict__ g, const float* __restrict__ b,
    float* __restrict__ x)
{
    __shared__ float red[256];
    __shared__ float buf[Hv];
    int tok = blockIdx.x;
    int s = tok % Sv;
    int id = ids[tok];
    int tid = threadIdx.x;

    float sum = 0.f;
    #pragma unroll
    for (int i = 0; i < 3; i++) {
        int h = tid + i * 256;
        float v = ew[(size_t)id * Hv + h] + ep[(size_t)s * Hv + h] + et[h];
        buf[h] = v;
        sum += v;
    }
    sum = block_sum256(sum, red);
    float m = sum * (1.0f / Hv);
    float sq = 0.f;
    #pragma unroll
    for (int i = 0; i < 3; i++) {
        int h = tid + i * 256;
        float d = buf[h] - m;
        sq += d * d;
    }
    sq = block_sum256(sq, red);
    float rstd = rsqrtf(sq * (1.0f / Hv) + 1e-12f);
    #pragma unroll
    for (int i = 0; i < 3; i++) {
        int h = tid + i * 256;
        x[(size_t)tok * Hv + h] = (buf[h] - m) * rstd * g[h] + b[h];
    }
}

__global__ __launch_bounds__(256) void ln_residual_kernel(
    float* __restrict__ x, const float* __restrict__ delta,
    const float* __restrict__ g, const float* __restrict__ b)
{
    __shared__ float red[256];
    __shared__ float buf[Hv];
    int tok = blockIdx.x;
    int tid = threadIdx.x;
    size_t base = (size_t)tok * Hv;

    float sum = 0.f;
    #pragma unroll
    for (int i = 0; i < 3; i++) {
        int h = tid + i * 256;
        float v = x[base + h] + delta[base + h];
        buf[h] = v;
        sum += v;
    }
    sum = block_sum256(sum, red);
    float m = sum * (1.0f / Hv);
    float sq = 0.f;
    #pragma unroll
    for (int i = 0; i < 3; i++) {
        int h = tid + i * 256;
        float d = buf[h] - m;
        sq += d * d;
    }
    sq = block_sum256(sq, red);
    float rstd = rsqrtf(sq * (1.0f / Hv) + 1e-12f);
    #pragma unroll
    for (int i = 0; i < 3; i++) {
        int h = tid + i * 256;
        x[base + h] = (buf[h] - m) * rstd * g[h] + b[h];
    }
}

// ---------------- fused attention -------------------------------------------
#define QBLK 8
__global__ __launch_bounds__(256) void attn_kernel(
    const float* __restrict__ q, const float* __restrict__ k,
    const float* __restrict__ v, const int* __restrict__ mask,
    float* __restrict__ ctx)
{
    __shared__ float kv[Sv][65];
    __shared__ float qs[QBLK][64];
    __shared__ float p [QBLK][132];
    const int b = blockIdx.z, h = blockIdx.y, q0 = blockIdx.x * QBLK;
    const int tid = threadIdx.x;
    const int w = tid >> 5, lane = tid & 31;

    for (int idx = tid; idx < QBLK * 64; idx += 256) {
        int r = idx >> 6, c = idx & 63;
        qs[r][c] = q[(size_t)(b * Sv + q0 + r) * Hv + h * 64 + c];
    }
    for (int idx = tid; idx < Sv * 64; idx += 256) {
        int r = idx >> 6, c = idx & 63;
        kv[r][c] = k[(size_t)(b * Sv + r) * Hv + h * 64 + c];
    }
    __syncthreads();

    float sc[4];
    #pragma unroll
    for (int j = 0; j < 4; j++) {
        int key = lane + 32 * j;
        float s = 0.f;
        #pragma unroll
        for (int d = 0; d < 64; d++) s += qs[w][d] * kv[key][d];
        s *= 0.125f;
        s += (1.0f - (float)mask[b * Sv + key]) * -1e9f;
        sc[j] = s;
    }
    float mx = fmaxf(fmaxf(sc[0], sc[1]), fmaxf(sc[2], sc[3]));
    #pragma unroll
    for (int o = 16; o > 0; o >>= 1) mx = fmaxf(mx, __shfl_xor_sync(0xffffffffu, mx, o));
    float sum = 0.f;
    #pragma unroll
    for (int j = 0; j < 4; j++) { sc[j] = expf(sc[j] - mx); sum += sc[j]; }
    #pragma unroll
    for (int o = 16; o > 0; o >>= 1) sum += __shfl_xor_sync(0xffffffffu, sum, o);
    float inv = 1.0f / sum;
    #pragma unroll
    for (int j = 0; j < 4; j++) p[w][lane + 32 * j] = sc[j] * inv;
    __syncthreads();

    for (int idx = tid; idx < Sv * 64; idx += 256) {
        int r = idx >> 6, c = idx & 63;
        kv[r][c] = v[(size_t)(b * Sv + r) * Hv + h * 64 + c];
    }
    __syncthreads();

    float acc0 = 0.f, acc1 = 0.f;
    #pragma unroll 4
    for (int key = 0; key < Sv; key++) {
        float pw = p[w][key];
        acc0 += pw * kv[key][lane];
        acc1 += pw * kv[key][lane + 32];
    }
    size_t base = (size_t)(b * Sv + q0 + w) * Hv + h * 64;
    ctx[base + lane]      = acc0;
    ctx[base + lane + 32] = acc1;
}

// ---------------- decoder pieces ---------------------------------------------
__global__ __launch_bounds__(256) void copy_hidden_kernel(
    const float* __restrict__ x, float* __restrict__ h)
{
    int idx = blockIdx.x * 256 + threadIdx.x;
    int b = idx / Hv, j = idx % Hv;
    h[idx] = x[(size_t)(b * Sv + (Sv - 1)) * Hv + j];
}

__global__ __launch_bounds__(256) void dec_init_kernel(
    const float* __restrict__ ew, const float* __restrict__ ep,
    const float* __restrict__ et, const float* __restrict__ g,
    const float* __restrict__ b, float* __restrict__ xt)
{
    __shared__ float red[256];
    __shared__ float buf[Hv];
    int bb = blockIdx.x;
    int tid = threadIdx.x;
    float sum = 0.f;
    #pragma unroll
    for (int i = 0; i < 3; i++) {
        int h = tid + i * 256;
        float v = ew[(size_t)CLSv * Hv + h] + ep[h] + et[h];
        buf[h] = v;
        sum += v;
    }
    sum = block_sum256(sum, red);
    float m = sum * (1.0f / Hv);
    float sq = 0.f;
    #pragma unroll
    for (int i = 0; i < 3; i++) {
        int h = tid + i * 256;
        float d = buf[h] - m;
        sq += d * d;
    }
    sq = block_sum256(sq, red);
    float rstd = rsqrtf(sq * (1.0f / Hv) + 1e-12f);
    #pragma unroll
    for (int i = 0; i < 3; i++) {
        int h = tid + i * 256;
        xt[(size_t)bb * Hv + h] = (buf[h] - m) * rstd * g[h] + b[h];
    }
}

__device__ __forceinline__ float sigmf(float x) { return 1.0f / (1.0f + expf(-x)); }

__global__ __launch_bounds__(256) void gru_elem_kernel(
    const float* __restrict__ gi, const float* __restrict__ gh,
    float* __restrict__ h, float* __restrict__ xt)
{
    int idx = blockIdx.x * 256 + threadIdx.x;
    int b = idx / Hv, j = idx % Hv;
    size_t base = (size_t)b * 3 * Hv;
    float r = sigmf(gi[base + j]          + gh[base + j]);
    float z = sigmf(gi[base + Hv + j]     + gh[base + Hv + j]);
    float n = tanhf(gi[base + 2*Hv + j] + r * gh[base + 2*Hv + j]);
    float hn = (1.0f - z) * n + z * h[idx];
    h[idx]  = hn;
    xt[idx] = hn;
}

// ---------------- launch orchestration ----------------------------------------
extern "C" void kernel_launch(void* const* d_in, const int* in_sizes, int n_in,
                              void* d_out, int out_size)
{
    const int*   ids      = (const int*)  d_in[0];
    const int*   amask    = (const int*)  d_in[1];
    const float* emb_word = (const float*)d_in[2];
    const float* emb_pos  = (const float*)d_in[3];
    const float* emb_tok  = (const float*)d_in[4];
    const float* ln_emb_g = (const float*)d_in[5];
    const float* ln_emb_b = (const float*)d_in[6];
    const float* Wq       = (const float*)d_in[7];
    const float* Wk       = (const float*)d_in[8];
    const float* Wv       = (const float*)d_in[9];
    const float* Wo       = (const float*)d_in[10];
    const float* bq       = (const float*)d_in[11];
    const float* bk       = (const float*)d_in[12];
    const float* bv       = (const float*)d_in[13];
    const float* bo       = (const float*)d_in[14];
    const float* ln1_g    = (const float*)d_in[15];
    const float* ln1_b    = (const float*)d_in[16];
    const float* W1       = (const float*)d_in[17];
    const float* b1       = (const float*)d_in[18];
    const float* W2       = (const float*)d_in[19];
    const float* b2       = (const float*)d_in[20];
    const float* ln2_g    = (const float*)d_in[21];
    const float* ln2_b    = (const float*)d_in[22];
    const float* W_ih     = (const float*)d_in[23];
    const float* W_hh     = (const float*)d_in[24];
    const float* b_ih     = (const float*)d_in[25];
    const float* b_hh     = (const float*)d_in[26];
    const float* Wf       = (const float*)d_in[27];
    const float* bf       = (const float*)d_in[28];
    float* out = (float*)d_out;

    float *x, *q, *k, *v, *ctx, *t1, *ff, *xt, *h, *gi, *gh;
    cudaGetSymbolAddress((void**)&x,   g_x);
    cudaGetSymbolAddress((void**)&q,   g_q);
    cudaGetSymbolAddress((void**)&k,   g_k);
    cudaGetSymbolAddress((void**)&v,   g_v);
    cudaGetSymbolAddress((void**)&ctx, g_ctx);
    cudaGetSymbolAddress((void**)&t1,  g_t1);
    cudaGetSymbolAddress((void**)&ff,  g_ff);
    cudaGetSymbolAddress((void**)&xt,  g_xt);
    cudaGetSymbolAddress((void**)&h,   g_h);
    cudaGetSymbolAddress((void**)&gi,  g_gi);
    cudaGetSymbolAddress((void**)&gh,  g_gh);

    embed_ln_kernel<<<NTOK, 256>>>(ids, emb_word, emb_pos, emb_tok,
                                   ln_emb_g, ln_emb_b, x);

    for (int l = 0; l < Lv; l++) {
        const float* wq = Wq + (size_t)l * Hv * Hv;
        const float* wk = Wk + (size_t)l * Hv * Hv;
        const float* wv = Wv + (size_t)l * Hv * Hv;
        const float* wo = Wo + (size_t)l * Hv * Hv;
        const float* w1 = W1 + (size_t)l * Hv * FFv;
        const float* w2 = W2 + (size_t)l * FFv * Hv;

        // fused QKV: one launch, gridDim.z = 3
        gemm_f16_kernel<0><<<tc_grid(NTOK, Hv, 3), 256>>>(
            x, wq, wk, wv, bq + l*Hv, bk + l*Hv, bv + l*Hv, q, k, v,
            NTOK, Hv, Hv);

        attn_kernel<<<dim3(Sv/QBLK, NHv, Bv), 256>>>(q, k, v, amask, ctx);

        gemm_f16_kernel<0><<<tc_grid(NTOK, Hv), 256>>>(
            ctx, wo, wo, wo, bo + l*Hv, bo + l*Hv, bo + l*Hv, t1, t1, t1,
            NTOK, Hv, Hv);
        ln_residual_kernel<<<NTOK, 256>>>(x, t1, ln1_g + l*Hv, ln1_b + l*Hv);

        gemm_f16_kernel<1><<<tc_grid(NTOK, FFv), 256>>>(
            x, w1, w1, w1, b1 + l*FFv, b1 + l*FFv, b1 + l*FFv, ff, ff, ff,
            NTOK, FFv, Hv);
        gemm_f16_kernel<0><<<tc_grid(NTOK, Hv), 256>>>(
            ff, w2, w2, w2, b2 + l*Hv, b2 + l*Hv, b2 + l*Hv, t1, t1, t1,
            NTOK, Hv, FFv);
        ln_residual_kernel<<<NTOK, 256>>>(x, t1, ln2_g + l*Hv, ln2_b + l*Hv);
    }

    copy_hidden_kernel<<<(Bv*Hv)/256, 256>>>(x, h);
    dec_init_kernel<<<Bv, 256>>>(emb_word, emb_pos, emb_tok, ln_emb_g, ln_emb_b, xt);

    for (int t = 0; t < Tv; t++) {
        gemm_kernel<true,0><<<gemm_grid(Bv, 3*Hv), 256>>>(xt, W_ih, b_ih, gi, Bv, 3*Hv, Hv, 3*Hv);
        gemm_kernel<true,0><<<gemm_grid(Bv, 3*Hv), 256>>>(h,  W_hh, b_hh, gh, Bv, 3*Hv, Hv, 3*Hv);
        gru_elem_kernel<<<(Bv*Hv)/256, 256>>>(gi, gh, h, xt);
        gemm_kernel<false,0><<<gemm_grid(Bv, Cv), 256>>>(h, Wf, bf, out + t*Cv, Bv, Cv, Hv, Tv*Cv);
    }
}

// round 9
// speedup vs baseline: 1.4927x; 1.4927x over previous
#include <cuda_runtime.h>
#include <cuda_fp16.h>
#include <cstdint>
#include <math.h>

// Problem dims
#define Bv   32
#define Sv   128
#define Hv   768
#define Lv   12
#define NHv  12
#define DHv  64
#define FFv  3072
#define Tv   10
#define Cv   16
#define CLSv 101

#define NTOK (Bv*Sv)          // 4096

// ---------------- scratch (device globals; no allocation allowed) ----------
__device__ __align__(16) float g_x  [NTOK*Hv];
__device__ __align__(16) float g_q  [NTOK*Hv];
__device__ __align__(16) float g_k  [NTOK*Hv];
__device__ __align__(16) float g_v  [NTOK*Hv];
__device__ __align__(16) float g_ctx[NTOK*Hv];
__device__ __align__(16) float g_t1 [NTOK*Hv];
__device__ __align__(16) float g_ff [NTOK*FFv];
__device__ __align__(16) float g_xt [Bv*Hv];
__device__ __align__(16) float g_h  [Bv*Hv];
__device__ __align__(16) float g_gi [Bv*3*Hv];
__device__ __align__(16) float g_gh [Bv*3*Hv];

// =================== FP16 tensor-core GEMM (m16n8k16) =======================
// C[M,N] = A[M,K] @ B[K,N] + bias (EPI=1: + exact GELU), fp32 accumulate.
// Inputs converted fp32->fp16 (RN) on the SMEM-store path; same 10-bit
// mantissa as TF32. Requires M%128==0, N%64==0, K%32==0.
// gridDim.z selects among 3 (B, bias, C) triples (QKV fusion).
//
// Block tile 128x64, 8 warps, warp tile 32x32, K-chunk 32 (2 k16 steps).
// SMEM (words): As[128][20] (32 halfs data + 8 pad), Bs[32][36] (64 halfs + 8 pad).
// A-frag reads bank-clean (20r+off); B via ldmatrix.x4.trans (rows 4k: clean).
// Structure per R4 (best known): prefetch -> compute -> sync -> store -> sync.

#define LDA_H 20
#define LDB_H 36

__device__ __forceinline__ uint32_t packh2(float lo, float hi) {
    __half2 h = __floats2half2_rn(lo, hi);   // lo -> .x (low half)
    return *reinterpret_cast<uint32_t*>(&h);
}

__device__ __forceinline__ void mma_f16(float c[4],
    uint32_t a0, uint32_t a1, uint32_t a2, uint32_t a3,
    uint32_t b0, uint32_t b1)
{
    asm volatile(
        "mma.sync.aligned.m16n8k16.row.col.f32.f16.f16.f32 "
        "{%0,%1,%2,%3}, {%4,%5,%6,%7}, {%8,%9}, {%0,%1,%2,%3};"
        : "+f"(c[0]), "+f"(c[1]), "+f"(c[2]), "+f"(c[3])
        : "r"(a0), "r"(a1), "r"(a2), "r"(a3), "r"(b0), "r"(b1));
}

__device__ __forceinline__ void ldsm4t(uint32_t& r0, uint32_t& r1,
                                       uint32_t& r2, uint32_t& r3, uint32_t addr)
{
    asm volatile("ldmatrix.sync.aligned.m8n8.x4.trans.shared.b16 {%0,%1,%2,%3}, [%4];"
        : "=r"(r0), "=r"(r1), "=r"(r2), "=r"(r3) : "r"(addr));
}

template<int EPI>
__global__ __launch_bounds__(256, 2) void gemm_f16_kernel(
    const float* __restrict__ A,
    const float* __restrict__ B0, const float* __restrict__ B1, const float* __restrict__ B2,
    const float* __restrict__ bias0, const float* __restrict__ bias1, const float* __restrict__ bias2,
    float* __restrict__ C0, float* __restrict__ C1, float* __restrict__ C2,
    int M, int N, int K)
{
    const int z = blockIdx.z;
    const float* B    = (z == 0) ? B0    : (z == 1) ? B1    : B2;
    const float* bias = (z == 0) ? bias0 : (z == 1) ? bias1 : bias2;
    float*       C    = (z == 0) ? C0    : (z == 1) ? C1    : C2;

    __shared__ uint32_t As[128 * LDA_H];   // 10 KB
    __shared__ uint32_t Bs[32 * LDB_H];    // 4.5 KB

    const int tid  = threadIdx.x;
    const int bm   = blockIdx.y * 128;
    const int bn   = blockIdx.x * 64;
    const int w    = tid >> 5, lane = tid & 31;
    const int warpM = w & 3;            // rows warpM*32
    const int warpN = w >> 2;           // cols warpN*32
    const int r    = lane >> 2;         // 0..7
    const int off  = lane & 3;          // 0..3

    // writer assignments (same global-coalesced pattern as R4)
    const int amrow = tid >> 3, ac = tid & 7;     // A rows amrow+32i, k-halfs 4ac..+3
    const int bkrow = tid >> 4, be = tid & 15;    // B k-rows bkrow+16i, n-halfs 4be..+3

    const float* Abase = A + (size_t)bm * K;
    const float* Bbase = B + bn;

    // A-frag reader base (word units)
    const int aBase = (warpM * 32 + r) * LDA_H + off;
    // B ldmatrix per-thread base byte address:
    //   row k = lane&15, col halfs = warpN*32 + ((lane>>4)&1)*8
    const uint32_t bs0 = (uint32_t)__cvta_generic_to_shared(Bs);
    const uint32_t ldsmBase = bs0 +
        (uint32_t)(((lane & 15) * LDB_H + warpN * 16 + ((lane >> 4) & 1) * 4) * 4);

    float4 ra[4], rb[2];

    // ---- prologue: load chunk 0, store ----
    #pragma unroll
    for (int i = 0; i < 4; i++)
        ra[i] = *(const float4*)(Abase + (size_t)(amrow + i * 32) * K + ac * 4);
    #pragma unroll
    for (int i = 0; i < 2; i++)
        rb[i] = *(const float4*)(Bbase + (size_t)(bkrow + i * 16) * N + be * 4);

    #pragma unroll
    for (int i = 0; i < 4; i++) {
        int m = amrow + i * 32;
        *(uint2*)&As[m * LDA_H + 2 * ac] =
            make_uint2(packh2(ra[i].x, ra[i].y), packh2(ra[i].z, ra[i].w));
    }
    #pragma unroll
    for (int i = 0; i < 2; i++) {
        int k = bkrow + i * 16;
        *(uint2*)&Bs[k * LDB_H + 2 * be] =
            make_uint2(packh2(rb[i].x, rb[i].y), packh2(rb[i].z, rb[i].w));
    }
    __syncthreads();

    float acc[2][4][4] = {};
    const int nk = K >> 5;

    #pragma unroll 1
    for (int ch = 0; ch < nk; ch++) {
        const bool has_next = (ch + 1) < nk;
        if (has_next) {
            int kk = (ch + 1) * 32;
            #pragma unroll
            for (int i = 0; i < 4; i++)
                ra[i] = *(const float4*)(Abase + (size_t)(amrow + i * 32) * K + kk + ac * 4);
            #pragma unroll
            for (int i = 0; i < 2; i++)
                rb[i] = *(const float4*)(Bbase + (size_t)(kk + bkrow + i * 16) * N + be * 4);
        }

        #pragma unroll
        for (int ks = 0; ks < 2; ks++) {
            // B fragments: two ldmatrix.x4.trans cover nt=0..3
            uint32_t bf[4][2];
            uint32_t baddr = ldsmBase + (uint32_t)(ks * 16 * LDB_H * 4);
            ldsm4t(bf[0][0], bf[0][1], bf[1][0], bf[1][1], baddr);
            ldsm4t(bf[2][0], bf[2][1], bf[3][0], bf[3][1], baddr + 32);

            // A fragments: 4 LDS.32 each, bank-clean, immediate offsets
            uint32_t af[2][4];
            #pragma unroll
            for (int mt = 0; mt < 2; mt++) {
                int b0i = aBase + mt * (16 * LDA_H) + ks * 8;
                af[mt][0] = As[b0i];
                af[mt][1] = As[b0i + 8 * LDA_H];
                af[mt][2] = As[b0i + 4];
                af[mt][3] = As[b0i + 8 * LDA_H + 4];
            }
            #pragma unroll
            for (int mt = 0; mt < 2; mt++)
                #pragma unroll
                for (int nt = 0; nt < 4; nt++)
                    mma_f16(acc[mt][nt], af[mt][0], af[mt][1], af[mt][2], af[mt][3],
                            bf[nt][0], bf[nt][1]);
        }
        __syncthreads();

        if (has_next) {
            #pragma unroll
            for (int i = 0; i < 4; i++) {
                int m = amrow + i * 32;
                *(uint2*)&As[m * LDA_H + 2 * ac] =
                    make_uint2(packh2(ra[i].x, ra[i].y), packh2(ra[i].z, ra[i].w));
            }
            #pragma unroll
            for (int i = 0; i < 2; i++) {
                int k = bkrow + i * 16;
                *(uint2*)&Bs[k * LDB_H + 2 * be] =
                    make_uint2(packh2(rb[i].x, rb[i].y), packh2(rb[i].z, rb[i].w));
            }
            __syncthreads();
        }
    }

    // epilogue (same fragment->C mapping as k8 path)
    #pragma unroll
    for (int mt = 0; mt < 2; mt++) {
        #pragma unroll
        for (int nt = 0; nt < 4; nt++) {
            int row0 = bm + warpM * 32 + mt * 16 + r;
            int col  = bn + warpN * 32 + nt * 8 + off * 2;
            float b0 = bias[col], b1 = bias[col + 1];
            float v00 = acc[mt][nt][0] + b0;
            float v01 = acc[mt][nt][1] + b1;
            float v10 = acc[mt][nt][2] + b0;
            float v11 = acc[mt][nt][3] + b1;
            if (EPI == 1) {
                v00 = 0.5f * v00 * (1.0f + erff(v00 * 0.70710678118654752f));
                v01 = 0.5f * v01 * (1.0f + erff(v01 * 0.70710678118654752f));
                v10 = 0.5f * v10 * (1.0f + erff(v10 * 0.70710678118654752f));
                v11 = 0.5f * v11 * (1.0f + erff(v11 * 0.70710678118654752f));
            }
            *(float2*)(C + (size_t)row0 * N + col)       = make_float2(v00, v01);
            *(float2*)(C + (size_t)(row0 + 8) * N + col) = make_float2(v10, v11);
        }
    }
}

static inline dim3 tc_grid(int M, int N, int z = 1) { return dim3(N / 64, M / 128, z); }

// =================== FFMA GEMM (small / decoder shapes) =====================
template<bool TRANSB, int EPI>
__global__ __launch_bounds__(256) void gemm_kernel(
    const float* __restrict__ A, const float* __restrict__ B,
    const float* __restrict__ bias, float* __restrict__ C,
    int M, int N, int K, int ldc)
{
    __shared__ float As[16][64];
    __shared__ float Bs[16][64];
    const int tid = threadIdx.x;
    const int bm = blockIdx.y * 64, bn = blockIdx.x * 64;
    const int ty = tid >> 4, tx = tid & 15;

    const int lm  = tid >> 2;
    const int lk4 = (tid & 3) * 4;
    const int lbk = tid >> 4;
    const int lbn4 = (tid & 15) * 4;

    float acc[4][4] = {};

    for (int kk = 0; kk < K; kk += 16) {
        float4 av = make_float4(0.f,0.f,0.f,0.f);
        if (bm + lm < M)
            av = *(const float4*)(A + (size_t)(bm + lm) * K + kk + lk4);
        As[lk4+0][lm] = av.x; As[lk4+1][lm] = av.y;
        As[lk4+2][lm] = av.z; As[lk4+3][lm] = av.w;

        if (TRANSB) {
            float4 bvv = make_float4(0.f,0.f,0.f,0.f);
            if (bn + lm < N)
                bvv = *(const float4*)(B + (size_t)(bn + lm) * K + kk + lk4);
            Bs[lk4+0][lm] = bvv.x; Bs[lk4+1][lm] = bvv.y;
            Bs[lk4+2][lm] = bvv.z; Bs[lk4+3][lm] = bvv.w;
        } else {
            float4 bvv = make_float4(0.f,0.f,0.f,0.f);
            if (bn + lbn4 < N)
                bvv = *(const float4*)(B + (size_t)(kk + lbk) * N + bn + lbn4);
            *(float4*)&Bs[lbk][lbn4] = bvv;
        }
        __syncthreads();

        #pragma unroll
        for (int k = 0; k < 16; k++) {
            float4 a = *(const float4*)&As[k][ty * 4];
            float4 b = *(const float4*)&Bs[k][tx * 4];
            acc[0][0] += a.x*b.x; acc[0][1] += a.x*b.y; acc[0][2] += a.x*b.z; acc[0][3] += a.x*b.w;
            acc[1][0] += a.y*b.x; acc[1][1] += a.y*b.y; acc[1][2] += a.y*b.z; acc[1][3] += a.y*b.w;
            acc[2][0] += a.z*b.x; acc[2][1] += a.z*b.y; acc[2][2] += a.z*b.z; acc[2][3] += a.z*b.w;
            acc[3][0] += a.w*b.x; acc[3][1] += a.w*b.y; acc[3][2] += a.w*b.z; acc[3][3] += a.w*b.w;
        }
        __syncthreads();
    }

    #pragma unroll
    for (int i = 0; i < 4; i++) {
        int row = bm + ty * 4 + i;
        if (row >= M) continue;
        #pragma unroll
        for (int j = 0; j < 4; j++) {
            int col = bn + tx * 4 + j;
            if (col >= N) continue;
            float vv = acc[i][j] + bias[col];
            if (EPI == 1) vv = 0.5f * vv * (1.0f + erff(vv * 0.70710678118654752f));
            C[(size_t)row * ldc + col] = vv;
        }
    }
}

static inline dim3 gemm_grid(int M, int N) { return dim3((N + 63) / 64, (M + 63) / 64); }

// ---------------- LayerNorm helpers ----------------------------------------
__device__ __forceinline__ float block_sum256(float v, float* red) {
    int tid = threadIdx.x;
    red[tid] = v;
    __syncthreads();
    #pragma unroll
    for (int s = 128; s > 0; s >>= 1) {
        if (tid < s) red[tid] += red[tid + s];
        __syncthreads();
    }
    float r = red[0];
    __syncthreads();
    return r;
}

__global__ __launch_bounds__(256) void embed_ln_kernel(
    const int* __restrict__ ids, const float* __restrict__ ew,
    const float* __restrict__ ep, const float* __restrict__ et,
    const float* __restrict__ g, const float* __restrict__ b,
    float* __restrict__ x)
{
    __shared__ float red[256];
    __shared__ float buf[Hv];
    int tok = blockIdx.x;
    int s = tok % Sv;
    int id = ids[tok];
    int tid = threadIdx.x;

    float sum = 0.f;
    #pragma unroll
    for (int i = 0; i < 3; i++) {
        int h = tid + i * 256;
        float v = ew[(size_t)id * Hv + h] + ep[(size_t)s * Hv + h] + et[h];
        buf[h] = v;
        sum += v;
    }
    sum = block_sum256(sum, red);
    float m = sum * (1.0f / Hv);
    float sq = 0.f;
    #pragma unroll
    for (int i = 0; i < 3; i++) {
        int h = tid + i * 256;
        float d = buf[h] - m;
        sq += d * d;
    }
    sq = block_sum256(sq, red);
    float rstd = rsqrtf(sq * (1.0f / Hv) + 1e-12f);
    #pragma unroll
    for (int i = 0; i < 3; i++) {
        int h = tid + i * 256;
        x[(size_t)tok * Hv + h] = (buf[h] - m) * rstd * g[h] + b[h];
    }
}

__global__ __launch_bounds__(256) void ln_residual_kernel(
    float* __restrict__ x, const float* __restrict__ delta,
    const float* __restrict__ g, const float* __restrict__ b)
{
    __shared__ float red[256];
    __shared__ float buf[Hv];
    int tok = blockIdx.x;
    int tid = threadIdx.x;
    size_t base = (size_t)tok * Hv;

    float sum = 0.f;
    #pragma unroll
    for (int i = 0; i < 3; i++) {
        int h = tid + i * 256;
        float v = x[base + h] + delta[base + h];
        buf[h] = v;
        sum += v;
    }
    sum = block_sum256(sum, red);
    float m = sum * (1.0f / Hv);
    float sq = 0.f;
    #pragma unroll
    for (int i = 0; i < 3; i++) {
        int h = tid + i * 256;
        float d = buf[h] - m;
        sq += d * d;
    }
    sq = block_sum256(sq, red);
    float rstd = rsqrtf(sq * (1.0f / Hv) + 1e-12f);
    #pragma unroll
    for (int i = 0; i < 3; i++) {
        int h = tid + i * 256;
        x[base + h] = (buf[h] - m) * rstd * g[h] + b[h];
    }
}

// ---------------- fused attention -------------------------------------------
#define QBLK 8
__global__ __launch_bounds__(256) void attn_kernel(
    const float* __restrict__ q, const float* __restrict__ k,
    const float* __restrict__ v, const int* __restrict__ mask,
    float* __restrict__ ctx)
{
    __shared__ float kv[Sv][65];
    __shared__ float qs[QBLK][64];
    __shared__ float p [QBLK][132];
    const int b = blockIdx.z, h = blockIdx.y, q0 = blockIdx.x * QBLK;
    const int tid = threadIdx.x;
    const int w = tid >> 5, lane = tid & 31;

    for (int idx = tid; idx < QBLK * 64; idx += 256) {
        int r = idx >> 6, c = idx & 63;
        qs[r][c] = q[(size_t)(b * Sv + q0 + r) * Hv + h * 64 + c];
    }
    for (int idx = tid; idx < Sv * 64; idx += 256) {
        int r = idx >> 6, c = idx & 63;
        kv[r][c] = k[(size_t)(b * Sv + r) * Hv + h * 64 + c];
    }
    __syncthreads();

    float sc[4];
    #pragma unroll
    for (int j = 0; j < 4; j++) {
        int key = lane + 32 * j;
        float s = 0.f;
        #pragma unroll
        for (int d = 0; d < 64; d++) s += qs[w][d] * kv[key][d];
        s *= 0.125f;
        s += (1.0f - (float)mask[b * Sv + key]) * -1e9f;
        sc[j] = s;
    }
    float mx = fmaxf(fmaxf(sc[0], sc[1]), fmaxf(sc[2], sc[3]));
    #pragma unroll
    for (int o = 16; o > 0; o >>= 1) mx = fmaxf(mx, __shfl_xor_sync(0xffffffffu, mx, o));
    float sum = 0.f;
    #pragma unroll
    for (int j = 0; j < 4; j++) { sc[j] = expf(sc[j] - mx); sum += sc[j]; }
    #pragma unroll
    for (int o = 16; o > 0; o >>= 1) sum += __shfl_xor_sync(0xffffffffu, sum, o);
    float inv = 1.0f / sum;
    #pragma unroll
    for (int j = 0; j < 4; j++) p[w][lane + 32 * j] = sc[j] * inv;
    __syncthreads();

    for (int idx = tid; idx < Sv * 64; idx += 256) {
        int r = idx >> 6, c = idx & 63;
        kv[r][c] = v[(size_t)(b * Sv + r) * Hv + h * 64 + c];
    }
    __syncthreads();

    float acc0 = 0.f, acc1 = 0.f;
    #pragma unroll 4
    for (int key = 0; key < Sv; key++) {
        float pw = p[w][key];
        acc0 += pw * kv[key][lane];
        acc1 += pw * kv[key][lane + 32];
    }
    size_t base = (size_t)(b * Sv + q0 + w) * Hv + h * 64;
    ctx[base + lane]      = acc0;
    ctx[base + lane + 32] = acc1;
}

// ---------------- decoder pieces ---------------------------------------------
__global__ __launch_bounds__(256) void copy_hidden_kernel(
    const float* __restrict__ x, float* __restrict__ h)
{
    int idx = blockIdx.x * 256 + threadIdx.x;
    int b = idx / Hv, j = idx % Hv;
    h[idx] = x[(size_t)(b * Sv + (Sv - 1)) * Hv + j];
}

__global__ __launch_bounds__(256) void dec_init_kernel(
    const float* __restrict__ ew, const float* __restrict__ ep,
    const float* __restrict__ et, const float* __restrict__ g,
    const float* __restrict__ b, float* __restrict__ xt)
{
    __shared__ float red[256];
    __shared__ float buf[Hv];
    int bb = blockIdx.x;
    int tid = threadIdx.x;
    float sum = 0.f;
    #pragma unroll
    for (int i = 0; i < 3; i++) {
        int h = tid + i * 256;
        float v = ew[(size_t)CLSv * Hv + h] + ep[h] + et[h];
        buf[h] = v;
        sum += v;
    }
    sum = block_sum256(sum, red);
    float m = sum * (1.0f / Hv);
    float sq = 0.f;
    #pragma unroll
    for (int i = 0; i < 3; i++) {
        int h = tid + i * 256;
        float d = buf[h] - m;
        sq += d * d;
    }
    sq = block_sum256(sq, red);
    float rstd = rsqrtf(sq * (1.0f / Hv) + 1e-12f);
    #pragma unroll
    for (int i = 0; i < 3; i++) {
        int h = tid + i * 256;
        xt[(size_t)bb * Hv + h] = (buf[h] - m) * rstd * g[h] + b[h];
    }
}

__device__ __forceinline__ float sigmf(float x) { return 1.0f / (1.0f + expf(-x)); }

__global__ __launch_bounds__(256) void gru_elem_kernel(
    const float* __restrict__ gi, const float* __restrict__ gh,
    float* __restrict__ h, float* __restrict__ xt)
{
    int idx = blockIdx.x * 256 + threadIdx.x;
    int b = idx / Hv, j = idx % Hv;
    size_t base = (size_t)b * 3 * Hv;
    float r = sigmf(gi[base + j]          + gh[base + j]);
    float z = sigmf(gi[base + Hv + j]     + gh[base + Hv + j]);
    float n = tanhf(gi[base + 2*Hv + j] + r * gh[base + 2*Hv + j]);
    float hn = (1.0f - z) * n + z * h[idx];
    h[idx]  = hn;
    xt[idx] = hn;
}

// ---------------- launch orchestration ----------------------------------------
extern "C" void kernel_launch(void* const* d_in, const int* in_sizes, int n_in,
                              void* d_out, int out_size)
{
    const int*   ids      = (const int*)  d_in[0];
    const int*   amask    = (const int*)  d_in[1];
    const float* emb_word = (const float*)d_in[2];
    const float* emb_pos  = (const float*)d_in[3];
    const float* emb_tok  = (const float*)d_in[4];
    const float* ln_emb_g = (const float*)d_in[5];
    const float* ln_emb_b = (const float*)d_in[6];
    const float* Wq       = (const float*)d_in[7];
    const float* Wk       = (const float*)d_in[8];
    const float* Wv       = (const float*)d_in[9];
    const float* Wo       = (const float*)d_in[10];
    const float* bq       = (const float*)d_in[11];
    const float* bk       = (const float*)d_in[12];
    const float* bv       = (const float*)d_in[13];
    const float* bo       = (const float*)d_in[14];
    const float* ln1_g    = (const float*)d_in[15];
    const float* ln1_b    = (const float*)d_in[16];
    const float* W1       = (const float*)d_in[17];
    const float* b1       = (const float*)d_in[18];
    const float* W2       = (const float*)d_in[19];
    const float* b2       = (const float*)d_in[20];
    const float* ln2_g    = (const float*)d_in[21];
    const float* ln2_b    = (const float*)d_in[22];
    const float* W_ih     = (const float*)d_in[23];
    const float* W_hh     = (const float*)d_in[24];
    const float* b_ih     = (const float*)d_in[25];
    const float* b_hh     = (const float*)d_in[26];
    const float* Wf       = (const float*)d_in[27];
    const float* bf       = (const float*)d_in[28];
    float* out = (float*)d_out;

    float *x, *q, *k, *v, *ctx, *t1, *ff, *xt, *h, *gi, *gh;
    cudaGetSymbolAddress((void**)&x,   g_x);
    cudaGetSymbolAddress((void**)&q,   g_q);
    cudaGetSymbolAddress((void**)&k,   g_k);
    cudaGetSymbolAddress((void**)&v,   g_v);
    cudaGetSymbolAddress((void**)&ctx, g_ctx);
    cudaGetSymbolAddress((void**)&t1,  g_t1);
    cudaGetSymbolAddress((void**)&ff,  g_ff);
    cudaGetSymbolAddress((void**)&xt,  g_xt);
    cudaGetSymbolAddress((void**)&h,   g_h);
    cudaGetSymbolAddress((void**)&gi,  g_gi);
    cudaGetSymbolAddress((void**)&gh,  g_gh);

    embed_ln_kernel<<<NTOK, 256>>>(ids, emb_word, emb_pos, emb_tok,
                                   ln_emb_g, ln_emb_b, x);

    for (int l = 0; l < Lv; l++) {
        const float* wq = Wq + (size_t)l * Hv * Hv;
        const float* wk = Wk + (size_t)l * Hv * Hv;
        const float* wv = Wv + (size_t)l * Hv * Hv;
        const float* wo = Wo + (size_t)l * Hv * Hv;
        const float* w1 = W1 + (size_t)l * Hv * FFv;
        const float* w2 = W2 + (size_t)l * FFv * Hv;

        // fused QKV: one launch, gridDim.z = 3
        gemm_f16_kernel<0><<<tc_grid(NTOK, Hv, 3), 256>>>(
            x, wq, wk, wv, bq + l*Hv, bk + l*Hv, bv + l*Hv, q, k, v,
            NTOK, Hv, Hv);

        attn_kernel<<<dim3(Sv/QBLK, NHv, Bv), 256>>>(q, k, v, amask, ctx);

        gemm_f16_kernel<0><<<tc_grid(NTOK, Hv), 256>>>(
            ctx, wo, wo, wo, bo + l*Hv, bo + l*Hv, bo + l*Hv, t1, t1, t1,
            NTOK, Hv, Hv);
        ln_residual_kernel<<<NTOK, 256>>>(x, t1, ln1_g + l*Hv, ln1_b + l*Hv);

        gemm_f16_kernel<1><<<tc_grid(NTOK, FFv), 256>>>(
            x, w1, w1, w1, b1 + l*FFv, b1 + l*FFv, b1 + l*FFv, ff, ff, ff,
            NTOK, FFv, Hv);
        gemm_f16_kernel<0><<<tc_grid(NTOK, Hv), 256>>>(
            ff, w2, w2, w2, b2 + l*Hv, b2 + l*Hv, b2 + l*Hv, t1, t1, t1,
            NTOK, Hv, FFv);
        ln_residual_kernel<<<NTOK, 256>>>(x, t1, ln2_g + l*Hv, ln2_b + l*Hv);
    }

    copy_hidden_kernel<<<(Bv*Hv)/256, 256>>>(x, h);
    dec_init_kernel<<<Bv, 256>>>(emb_word, emb_pos, emb_tok, ln_emb_g, ln_emb_b, xt);

    for (int t = 0; t < Tv; t++) {
        gemm_kernel<true,0><<<gemm_grid(Bv, 3*Hv), 256>>>(xt, W_ih, b_ih, gi, Bv, 3*Hv, Hv, 3*Hv);
        gemm_kernel<true,0><<<gemm_grid(Bv, 3*Hv), 256>>>(h,  W_hh, b_hh, gh, Bv, 3*Hv, Hv, 3*Hv);
        gru_elem_kernel<<<(Bv*Hv)/256, 256>>>(gi, gh, h, xt);
        gemm_kernel<false,0><<<gemm_grid(Bv, Cv), 256>>>(h, Wf, bf, out + t*Cv, Bv, Cv, Hv, Tv*Cv);
    }
}

// round 10
// speedup vs baseline: 1.5006x; 1.0053x over previous
#include <cuda_runtime.h>
#include <cuda_fp16.h>
#include <cstdint>
#include <math.h>

// Problem dims
#define Bv   32
#define Sv   128
#define Hv   768
#define Lv   12
#define NHv  12
#define DHv  64
#define FFv  3072
#define Tv   10
#define Cv   16
#define CLSv 101

#define NTOK (Bv*Sv)          // 4096

// ---------------- scratch (device globals; no allocation allowed) ----------
__device__ __align__(16) float g_x  [NTOK*Hv];
__device__ __align__(16) float g_q  [NTOK*Hv];
__device__ __align__(16) float g_k  [NTOK*Hv];
__device__ __align__(16) float g_v  [NTOK*Hv];
__device__ __align__(16) float g_ctx[NTOK*Hv];
__device__ __align__(16) float g_t1 [NTOK*Hv];
__device__ __align__(16) float g_ff [NTOK*FFv];
__device__ __align__(16) float g_xt [Bv*Hv];
__device__ __align__(16) float g_h  [Bv*Hv];
__device__ __align__(16) float g_gi [Bv*3*Hv];
__device__ __align__(16) float g_gh [Bv*3*Hv];

// =================== FP16 tensor-core GEMM (m16n8k16) =======================
// C[M,N] = A[M,K] @ B[K,N] + bias (EPI=1: + exact GELU), fp32 accumulate.
// Inputs converted fp32->fp16 (RN) on the SMEM-store path; same 10-bit
// mantissa as TF32. Requires M%128==0, N%64==0, K%32==0.
// gridDim.z selects among 3 (B, bias, C) triples (QKV fusion).
//
// Block tile 128x64, 8 warps, warp tile 32x32, K-chunk 32 (2 k16 steps).
// SMEM (words): As[128][20] (32 halfs data + 8 pad), Bs[32][36] (64 halfs + 8 pad).
// A-frag reads bank-clean (20r+off); B via ldmatrix.x4.trans (rows 4k: clean).
// Structure per R4 (best known): prefetch -> compute -> sync -> store -> sync.

#define LDA_H 20
#define LDB_H 36

__device__ __forceinline__ uint32_t packh2(float lo, float hi) {
    __half2 h = __floats2half2_rn(lo, hi);   // lo -> .x (low half)
    return *reinterpret_cast<uint32_t*>(&h);
}

__device__ __forceinline__ void mma_f16(float c[4],
    uint32_t a0, uint32_t a1, uint32_t a2, uint32_t a3,
    uint32_t b0, uint32_t b1)
{
    asm volatile(
        "mma.sync.aligned.m16n8k16.row.col.f32.f16.f16.f32 "
        "{%0,%1,%2,%3}, {%4,%5,%6,%7}, {%8,%9}, {%0,%1,%2,%3};"
        : "+f"(c[0]), "+f"(c[1]), "+f"(c[2]), "+f"(c[3])
        : "r"(a0), "r"(a1), "r"(a2), "r"(a3), "r"(b0), "r"(b1));
}

__device__ __forceinline__ void ldsm4t(uint32_t& r0, uint32_t& r1,
                                       uint32_t& r2, uint32_t& r3, uint32_t addr)
{
    asm volatile("ldmatrix.sync.aligned.m8n8.x4.trans.shared.b16 {%0,%1,%2,%3}, [%4];"
        : "=r"(r0), "=r"(r1), "=r"(r2), "=r"(r3) : "r"(addr));
}

template<int EPI>
__global__ __launch_bounds__(256, 2) void gemm_f16_kernel(
    const float* __restrict__ A,
    const float* __restrict__ B0, const float* __restrict__ B1, const float* __restrict__ B2,
    const float* __restrict__ bias0, const float* __restrict__ bias1, const float* __restrict__ bias2,
    float* __restrict__ C0, float* __restrict__ C1, float* __restrict__ C2,
    int M, int N, int K)
{
    const int z = blockIdx.z;
    const float* B    = (z == 0) ? B0    : (z == 1) ? B1    : B2;
    const float* bias = (z == 0) ? bias0 : (z == 1) ? bias1 : bias2;
    float*       C    = (z == 0) ? C0    : (z == 1) ? C1    : C2;

    __shared__ uint32_t As[128 * LDA_H];   // 10 KB
    __shared__ uint32_t Bs[32 * LDB_H];    // 4.5 KB

    const int tid  = threadIdx.x;
    const int bm   = blockIdx.y * 128;
    const int bn   = blockIdx.x * 64;
    const int w    = tid >> 5, lane = tid & 31;
    const int warpM = w & 3;            // rows warpM*32
    const int warpN = w >> 2;           // cols warpN*32
    const int r    = lane >> 2;         // 0..7
    const int off  = lane & 3;          // 0..3

    // writer assignments (same global-coalesced pattern as R4)
    const int amrow = tid >> 3, ac = tid & 7;     // A rows amrow+32i, k-halfs 4ac..+3
    const int bkrow = tid >> 4, be = tid & 15;    // B k-rows bkrow+16i, n-halfs 4be..+3

    const float* Abase = A + (size_t)bm * K;
    const float* Bbase = B + bn;

    // A-frag reader base (word units)
    const int aBase = (warpM * 32 + r) * LDA_H + off;
    // B ldmatrix per-thread base byte address:
    //   row k = lane&15, col halfs = warpN*32 + ((lane>>4)&1)*8
    const uint32_t bs0 = (uint32_t)__cvta_generic_to_shared(Bs);
    const uint32_t ldsmBase = bs0 +
        (uint32_t)(((lane & 15) * LDB_H + warpN * 16 + ((lane >> 4) & 1) * 4) * 4);

    float4 ra[4], rb[2];

    // ---- prologue: load chunk 0, store ----
    #pragma unroll
    for (int i = 0; i < 4; i++)
        ra[i] = *(const float4*)(Abase + (size_t)(amrow + i * 32) * K + ac * 4);
    #pragma unroll
    for (int i = 0; i < 2; i++)
        rb[i] = *(const float4*)(Bbase + (size_t)(bkrow + i * 16) * N + be * 4);

    #pragma unroll
    for (int i = 0; i < 4; i++) {
        int m = amrow + i * 32;
        *(uint2*)&As[m * LDA_H + 2 * ac] =
            make_uint2(packh2(ra[i].x, ra[i].y), packh2(ra[i].z, ra[i].w));
    }
    #pragma unroll
    for (int i = 0; i < 2; i++) {
        int k = bkrow + i * 16;
        *(uint2*)&Bs[k * LDB_H + 2 * be] =
            make_uint2(packh2(rb[i].x, rb[i].y), packh2(rb[i].z, rb[i].w));
    }
    __syncthreads();

    float acc[2][4][4] = {};
    const int nk = K >> 5;

    #pragma unroll 1
    for (int ch = 0; ch < nk; ch++) {
        const bool has_next = (ch + 1) < nk;
        if (has_next) {
            int kk = (ch + 1) * 32;
            #pragma unroll
            for (int i = 0; i < 4; i++)
                ra[i] = *(const float4*)(Abase + (size_t)(amrow + i * 32) * K + kk + ac * 4);
            #pragma unroll
            for (int i = 0; i < 2; i++)
                rb[i] = *(const float4*)(Bbase + (size_t)(kk + bkrow + i * 16) * N + be * 4);
        }

        #pragma unroll
        for (int ks = 0; ks < 2; ks++) {
            // B fragments: two ldmatrix.x4.trans cover nt=0..3
            uint32_t bf[4][2];
            uint32_t baddr = ldsmBase + (uint32_t)(ks * 16 * LDB_H * 4);
            ldsm4t(bf[0][0], bf[0][1], bf[1][0], bf[1][1], baddr);
            ldsm4t(bf[2][0], bf[2][1], bf[3][0], bf[3][1], baddr + 32);

            // A fragments: 4 LDS.32 each, bank-clean, immediate offsets
            uint32_t af[2][4];
            #pragma unroll
            for (int mt = 0; mt < 2; mt++) {
                int b0i = aBase + mt * (16 * LDA_H) + ks * 8;
                af[mt][0] = As[b0i];
                af[mt][1] = As[b0i + 8 * LDA_H];
                af[mt][2] = As[b0i + 4];
                af[mt][3] = As[b0i + 8 * LDA_H + 4];
            }
            #pragma unroll
            for (int mt = 0; mt < 2; mt++)
                #pragma unroll
                for (int nt = 0; nt < 4; nt++)
                    mma_f16(acc[mt][nt], af[mt][0], af[mt][1], af[mt][2], af[mt][3],
                            bf[nt][0], bf[nt][1]);
        }
        __syncthreads();

        if (has_next) {
            #pragma unroll
            for (int i = 0; i < 4; i++) {
                int m = amrow + i * 32;
                *(uint2*)&As[m * LDA_H + 2 * ac] =
                    make_uint2(packh2(ra[i].x, ra[i].y), packh2(ra[i].z, ra[i].w));
            }
            #pragma unroll
            for (int i = 0; i < 2; i++) {
                int k = bkrow + i * 16;
                *(uint2*)&Bs[k * LDB_H + 2 * be] =
                    make_uint2(packh2(rb[i].x, rb[i].y), packh2(rb[i].z, rb[i].w));
            }
            __syncthreads();
        }
    }

    // epilogue (same fragment->C mapping as k8 path)
    #pragma unroll
    for (int mt = 0; mt < 2; mt++) {
        #pragma unroll
        for (int nt = 0; nt < 4; nt++) {
            int row0 = bm + warpM * 32 + mt * 16 + r;
            int col  = bn + warpN * 32 + nt * 8 + off * 2;
            float b0 = bias[col], b1 = bias[col + 1];
            float v00 = acc[mt][nt][0] + b0;
            float v01 = acc[mt][nt][1] + b1;
            float v10 = acc[mt][nt][2] + b0;
            float v11 = acc[mt][nt][3] + b1;
            if (EPI == 1) {
                v00 = 0.5f * v00 * (1.0f + erff(v00 * 0.70710678118654752f));
                v01 = 0.5f * v01 * (1.0f + erff(v01 * 0.70710678118654752f));
                v10 = 0.5f * v10 * (1.0f + erff(v10 * 0.70710678118654752f));
                v11 = 0.5f * v11 * (1.0f + erff(v11 * 0.70710678118654752f));
            }
            *(float2*)(C + (size_t)row0 * N + col)       = make_float2(v00, v01);
            *(float2*)(C + (size_t)(row0 + 8) * N + col) = make_float2(v10, v11);
        }
    }
}

static inline dim3 tc_grid(int M, int N, int z = 1) { return dim3(N / 64, M / 128, z); }

// =================== FFMA GEMM (small / decoder shapes) =====================
template<bool TRANSB, int EPI>
__global__ __launch_bounds__(256) void gemm_kernel(
    const float* __restrict__ A, const float* __restrict__ B,
    const float* __restrict__ bias, float* __restrict__ C,
    int M, int N, int K, int ldc)
{
    __shared__ float As[16][64];
    __shared__ float Bs[16][64];
    const int tid = threadIdx.x;
    const int bm = blockIdx.y * 64, bn = blockIdx.x * 64;
    const int ty = tid >> 4, tx = tid & 15;

    const int lm  = tid >> 2;
    const int lk4 = (tid & 3) * 4;
    const int lbk = tid >> 4;
    const int lbn4 = (tid & 15) * 4;

    float acc[4][4] = {};

    for (int kk = 0; kk < K; kk += 16) {
        float4 av = make_float4(0.f,0.f,0.f,0.f);
        if (bm + lm < M)
            av = *(const float4*)(A + (size_t)(bm + lm) * K + kk + lk4);
        As[lk4+0][lm] = av.x; As[lk4+1][lm] = av.y;
        As[lk4+2][lm] = av.z; As[lk4+3][lm] = av.w;

        if (TRANSB) {
            float4 bvv = make_float4(0.f,0.f,0.f,0.f);
            if (bn + lm < N)
                bvv = *(const float4*)(B + (size_t)(bn + lm) * K + kk + lk4);
            Bs[lk4+0][lm] = bvv.x; Bs[lk4+1][lm] = bvv.y;
            Bs[lk4+2][lm] = bvv.z; Bs[lk4+3][lm] = bvv.w;
        } else {
            float4 bvv = make_float4(0.f,0.f,0.f,0.f);
            if (bn + lbn4 < N)
                bvv = *(const float4*)(B + (size_t)(kk + lbk) * N + bn + lbn4);
            *(float4*)&Bs[lbk][lbn4] = bvv;
        }
        __syncthreads();

        #pragma unroll
        for (int k = 0; k < 16; k++) {
            float4 a = *(const float4*)&As[k][ty * 4];
            float4 b = *(const float4*)&Bs[k][tx * 4];
            acc[0][0] += a.x*b.x; acc[0][1] += a.x*b.y; acc[0][2] += a.x*b.z; acc[0][3] += a.x*b.w;
            acc[1][0] += a.y*b.x; acc[1][1] += a.y*b.y; acc[1][2] += a.y*b.z; acc[1][3] += a.y*b.w;
            acc[2][0] += a.z*b.x; acc[2][1] += a.z*b.y; acc[2][2] += a.z*b.z; acc[2][3] += a.z*b.w;
            acc[3][0] += a.w*b.x; acc[3][1] += a.w*b.y; acc[3][2] += a.w*b.z; acc[3][3] += a.w*b.w;
        }
        __syncthreads();
    }

    #pragma unroll
    for (int i = 0; i < 4; i++) {
        int row = bm + ty * 4 + i;
        if (row >= M) continue;
        #pragma unroll
        for (int j = 0; j < 4; j++) {
            int col = bn + tx * 4 + j;
            if (col >= N) continue;
            float vv = acc[i][j] + bias[col];
            if (EPI == 1) vv = 0.5f * vv * (1.0f + erff(vv * 0.70710678118654752f));
            C[(size_t)row * ldc + col] = vv;
        }
    }
}

static inline dim3 gemm_grid(int M, int N) { return dim3((N + 63) / 64, (M + 63) / 64); }

// ---------------- LayerNorm helpers ----------------------------------------
__device__ __forceinline__ float block_sum256(float v, float* red) {
    int tid = threadIdx.x;
    red[tid] = v;
    __syncthreads();
    #pragma unroll
    for (int s = 128; s > 0; s >>= 1) {
        if (tid < s) red[tid] += red[tid + s];
        __syncthreads();
    }
    float r = red[0];
    __syncthreads();
    return r;
}

__global__ __launch_bounds__(256) void embed_ln_kernel(
    const int* __restrict__ ids, const float* __restrict__ ew,
    const float* __restrict__ ep, const float* __restrict__ et,
    const float* __restrict__ g, const float* __restrict__ b,
    float* __restrict__ x)
{
    __shared__ float red[256];
    __shared__ float buf[Hv];
    int tok = blockIdx.x;
    int s = tok % Sv;
    int id = ids[tok];
    int tid = threadIdx.x;

    float sum = 0.f;
    #pragma unroll
    for (int i = 0; i < 3; i++) {
        int h = tid + i * 256;
        float v = ew[(size_t)id * Hv + h] + ep[(size_t)s * Hv + h] + et[h];
        buf[h] = v;
        sum += v;
    }
    sum = block_sum256(sum, red);
    float m = sum * (1.0f / Hv);
    float sq = 0.f;
    #pragma unroll
    for (int i = 0; i < 3; i++) {
        int h = tid + i * 256;
        float d = buf[h] - m;
        sq += d * d;
    }
    sq = block_sum256(sq, red);
    float rstd = rsqrtf(sq * (1.0f / Hv) + 1e-12f);
    #pragma unroll
    for (int i = 0; i < 3; i++) {
        int h = tid + i * 256;
        x[(size_t)tok * Hv + h] = (buf[h] - m) * rstd * g[h] + b[h];
    }
}

__global__ __launch_bounds__(256) void ln_residual_kernel(
    float* __restrict__ x, const float* __restrict__ delta,
    const float* __restrict__ g, const float* __restrict__ b)
{
    __shared__ float red[256];
    __shared__ float buf[Hv];
    int tok = blockIdx.x;
    int tid = threadIdx.x;
    size_t base = (size_t)tok * Hv;

    float sum = 0.f;
    #pragma unroll
    for (int i = 0; i < 3; i++) {
        int h = tid + i * 256;
        float v = x[base + h] + delta[base + h];
        buf[h] = v;
        sum += v;
    }
    sum = block_sum256(sum, red);
    float m = sum * (1.0f / Hv);
    float sq = 0.f;
    #pragma unroll
    for (int i = 0; i < 3; i++) {
        int h = tid + i * 256;
        float d = buf[h] - m;
        sq += d * d;
    }
    sq = block_sum256(sq, red);
    float rstd = rsqrtf(sq * (1.0f / Hv) + 1e-12f);
    #pragma unroll
    for (int i = 0; i < 3; i++) {
        int h = tid + i * 256;
        x[base + h] = (buf[h] - m) * rstd * g[h] + b[h];
    }
}

// ---------------- fused attention -------------------------------------------
#define QBLK 8
__global__ __launch_bounds__(256) void attn_kernel(
    const float* __restrict__ q, const float* __restrict__ k,
    const float* __restrict__ v, const int* __restrict__ mask,
    float* __restrict__ ctx)
{
    __shared__ float kv[Sv][65];
    __shared__ float qs[QBLK][64];
    __shared__ float p [QBLK][132];
    const int b = blockIdx.z, h = blockIdx.y, q0 = blockIdx.x * QBLK;
    const int tid = threadIdx.x;
    const int w = tid >> 5, lane = tid & 31;

    for (int idx = tid; idx < QBLK * 64; idx += 256) {
        int r = idx >> 6, c = idx & 63;
        qs[r][c] = q[(size_t)(b * Sv + q0 + r) * Hv + h * 64 + c];
    }
    for (int idx = tid; idx < Sv * 64; idx += 256) {
        int r = idx >> 6, c = idx & 63;
        kv[r][c] = k[(size_t)(b * Sv + r) * Hv + h * 64 + c];
    }
    __syncthreads();

    float sc[4];
    #pragma unroll
    for (int j = 0; j < 4; j++) {
        int key = lane + 32 * j;
        float s = 0.f;
        #pragma unroll
        for (int d = 0; d < 64; d++) s += qs[w][d] * kv[key][d];
        s *= 0.125f;
        s += (1.0f - (float)mask[b * Sv + key]) * -1e9f;
        sc[j] = s;
    }
    float mx = fmaxf(fmaxf(sc[0], sc[1]), fmaxf(sc[2], sc[3]));
    #pragma unroll
    for (int o = 16; o > 0; o >>= 1) mx = fmaxf(mx, __shfl_xor_sync(0xffffffffu, mx, o));
    float sum = 0.f;
    #pragma unroll
    for (int j = 0; j < 4; j++) { sc[j] = expf(sc[j] - mx); sum += sc[j]; }
    #pragma unroll
    for (int o = 16; o > 0; o >>= 1) sum += __shfl_xor_sync(0xffffffffu, sum, o);
    float inv = 1.0f / sum;
    #pragma unroll
    for (int j = 0; j < 4; j++) p[w][lane + 32 * j] = sc[j] * inv;
    __syncthreads();

    for (int idx = tid; idx < Sv * 64; idx += 256) {
        int r = idx >> 6, c = idx & 63;
        kv[r][c] = v[(size_t)(b * Sv + r) * Hv + h * 64 + c];
    }
    __syncthreads();

    float acc0 = 0.f, acc1 = 0.f;
    #pragma unroll 4
    for (int key = 0; key < Sv; key++) {
        float pw = p[w][key];
        acc0 += pw * kv[key][lane];
        acc1 += pw * kv[key][lane + 32];
    }
    size_t base = (size_t)(b * Sv + q0 + w) * Hv + h * 64;
    ctx[base + lane]      = acc0;
    ctx[base + lane + 32] = acc1;
}

// ---------------- decoder pieces ---------------------------------------------
__global__ __launch_bounds__(256) void copy_hidden_kernel(
    const float* __restrict__ x, float* __restrict__ h)
{
    int idx = blockIdx.x * 256 + threadIdx.x;
    int b = idx / Hv, j = idx % Hv;
    h[idx] = x[(size_t)(b * Sv + (Sv - 1)) * Hv + j];
}

__global__ __launch_bounds__(256) void dec_init_kernel(
    const float* __restrict__ ew, const float* __restrict__ ep,
    const float* __restrict__ et, const float* __restrict__ g,
    const float* __restrict__ b, float* __restrict__ xt)
{
    __shared__ float red[256];
    __shared__ float buf[Hv];
    int bb = blockIdx.x;
    int tid = threadIdx.x;
    float sum = 0.f;
    #pragma unroll
    for (int i = 0; i < 3; i++) {
        int h = tid + i * 256;
        float v = ew[(size_t)CLSv * Hv + h] + ep[h] + et[h];
        buf[h] = v;
        sum += v;
    }
    sum = block_sum256(sum, red);
    float m = sum * (1.0f / Hv);
    float sq = 0.f;
    #pragma unroll
    for (int i = 0; i < 3; i++) {
        int h = tid + i * 256;
        float d = buf[h] - m;
        sq += d * d;
    }
    sq = block_sum256(sq, red);
    float rstd = rsqrtf(sq * (1.0f / Hv) + 1e-12f);
    #pragma unroll
    for (int i = 0; i < 3; i++) {
        int h = tid + i * 256;
        xt[(size_t)bb * Hv + h] = (buf[h] - m) * rstd * g[h] + b[h];
    }
}

__device__ __forceinline__ float sigmf(float x) { return 1.0f / (1.0f + expf(-x)); }

__global__ __launch_bounds__(256) void gru_elem_kernel(
    const float* __restrict__ gi, const float* __restrict__ gh,
    float* __restrict__ h, float* __restrict__ xt)
{
    int idx = blockIdx.x * 256 + threadIdx.x;
    int b = idx / Hv, j = idx % Hv;
    size_t base = (size_t)b * 3 * Hv;
    float r = sigmf(gi[base + j]          + gh[base + j]);
    float z = sigmf(gi[base + Hv + j]     + gh[base + Hv + j]);
    float n = tanhf(gi[base + 2*Hv + j] + r * gh[base + 2*Hv + j]);
    float hn = (1.0f - z) * n + z * h[idx];
    h[idx]  = hn;
    xt[idx] = hn;
}

// ---------------- launch orchestration ----------------------------------------
extern "C" void kernel_launch(void* const* d_in, const int* in_sizes, int n_in,
                              void* d_out, int out_size)
{
    const int*   ids      = (const int*)  d_in[0];
    const int*   amask    = (const int*)  d_in[1];
    const float* emb_word = (const float*)d_in[2];
    const float* emb_pos  = (const float*)d_in[3];
    const float* emb_tok  = (const float*)d_in[4];
    const float* ln_emb_g = (const float*)d_in[5];
    const float* ln_emb_b = (const float*)d_in[6];
    const float* Wq       = (const float*)d_in[7];
    const float* Wk       = (const float*)d_in[8];
    const float* Wv       = (const float*)d_in[9];
    const float* Wo       = (const float*)d_in[10];
    const float* bq       = (const float*)d_in[11];
    const float* bk       = (const float*)d_in[12];
    const float* bv       = (const float*)d_in[13];
    const float* bo       = (const float*)d_in[14];
    const float* ln1_g    = (const float*)d_in[15];
    const float* ln1_b    = (const float*)d_in[16];
    const float* W1       = (const float*)d_in[17];
    const float* b1       = (const float*)d_in[18];
    const float* W2       = (const float*)d_in[19];
    const float* b2       = (const float*)d_in[20];
    const float* ln2_g    = (const float*)d_in[21];
    const float* ln2_b    = (const float*)d_in[22];
    const float* W_ih     = (const float*)d_in[23];
    const float* W_hh     = (const float*)d_in[24];
    const float* b_ih     = (const float*)d_in[25];
    const float* b_hh     = (const float*)d_in[26];
    const float* Wf       = (const float*)d_in[27];
    const float* bf       = (const float*)d_in[28];
    float* out = (float*)d_out;

    float *x, *q, *k, *v, *ctx, *t1, *ff, *xt, *h, *gi, *gh;
    cudaGetSymbolAddress((void**)&x,   g_x);
    cudaGetSymbolAddress((void**)&q,   g_q);
    cudaGetSymbolAddress((void**)&k,   g_k);
    cudaGetSymbolAddress((void**)&v,   g_v);
    cudaGetSymbolAddress((void**)&ctx, g_ctx);
    cudaGetSymbolAddress((void**)&t1,  g_t1);
    cudaGetSymbolAddress((void**)&ff,  g_ff);
    cudaGetSymbolAddress((void**)&xt,  g_xt);
    cudaGetSymbolAddress((void**)&h,   g_h);
    cudaGetSymbolAddress((void**)&gi,  g_gi);
    cudaGetSymbolAddress((void**)&gh,  g_gh);

    embed_ln_kernel<<<NTOK, 256>>>(ids, emb_word, emb_pos, emb_tok,
                                   ln_emb_g, ln_emb_b, x);

    for (int l = 0; l < Lv; l++) {
        const float* wq = Wq + (size_t)l * Hv * Hv;
        const float* wk = Wk + (size_t)l * Hv * Hv;
        const float* wv = Wv + (size_t)l * Hv * Hv;
        const float* wo = Wo + (size_t)l * Hv * Hv;
        const float* w1 = W1 + (size_t)l * Hv * FFv;
        const float* w2 = W2 + (size_t)l * FFv * Hv;

        // fused QKV: one launch, gridDim.z = 3
        gemm_f16_kernel<0><<<tc_grid(NTOK, Hv, 3), 256>>>(
            x, wq, wk, wv, bq + l*Hv, bk + l*Hv, bv + l*Hv, q, k, v,
            NTOK, Hv, Hv);

        attn_kernel<<<dim3(Sv/QBLK, NHv, Bv), 256>>>(q, k, v, amask, ctx);

        gemm_f16_kernel<0><<<tc_grid(NTOK, Hv), 256>>>(
            ctx, wo, wo, wo, bo + l*Hv, bo + l*Hv, bo + l*Hv, t1, t1, t1,
            NTOK, Hv, Hv);
        ln_residual_kernel<<<NTOK, 256>>>(x, t1, ln1_g + l*Hv, ln1_b + l*Hv);

        gemm_f16_kernel<1><<<tc_grid(NTOK, FFv), 256>>>(
            x, w1, w1, w1, b1 + l*FFv, b1 + l*FFv, b1 + l*FFv, ff, ff, ff,
            NTOK, FFv, Hv);
        gemm_f16_kernel<0><<<tc_grid(NTOK, Hv), 256>>>(
            ff, w2, w2, w2, b2 + l*Hv, b2 + l*Hv, b2 + l*Hv, t1, t1, t1,
            NTOK, Hv, FFv);
        ln_residual_kernel<<<NTOK, 256>>>(x, t1, ln2_g + l*Hv, ln2_b + l*Hv);
    }

    copy_hidden_kernel<<<(Bv*Hv)/256, 256>>>(x, h);
    dec_init_kernel<<<Bv, 256>>>(emb_word, emb_pos, emb_tok, ln_emb_g, ln_emb_b, xt);

    for (int t = 0; t < Tv; t++) {
        gemm_kernel<true,0><<<gemm_grid(Bv, 3*Hv), 256>>>(xt, W_ih, b_ih, gi, Bv, 3*Hv, Hv, 3*Hv);
        gemm_kernel<true,0><<<gemm_grid(Bv, 3*Hv), 256>>>(h,  W_hh, b_hh, gh, Bv, 3*Hv, Hv, 3*Hv);
        gru_elem_kernel<<<(Bv*Hv)/256, 256>>>(gi, gh, h, xt);
        gemm_kernel<false,0><<<gemm_grid(Bv, Cv), 256>>>(h, Wf, bf, out + t*Cv, Bv, Cv, Hv, Tv*Cv);
    }
}

// round 11
// speedup vs baseline: 1.5020x; 1.0010x over previous
#include <cuda_runtime.h>
#include <cuda_fp16.h>
#include <cstdint>
#include <math.h>

// Problem dims
#define Bv   32
#define Sv   128
#define Hv   768
#define Lv   12
#define NHv  12
#define DHv  64
#define FFv  3072
#define Tv   10
#define Cv   16
#define CLSv 101

#define NTOK (Bv*Sv)          // 4096

// ---------------- scratch (device globals; no allocation allowed) ----------
__device__ __align__(16) float g_x  [NTOK*Hv];
__device__ __align__(16) float g_q  [NTOK*Hv];
__device__ __align__(16) float g_k  [NTOK*Hv];
__device__ __align__(16) float g_v  [NTOK*Hv];
__device__ __align__(16) float g_ctx[NTOK*Hv];
__device__ __align__(16) float g_t1 [NTOK*Hv];
__device__ __align__(16) float g_ff [NTOK*FFv];
__device__ __align__(16) float g_xt [Bv*Hv];
__device__ __align__(16) float g_h  [Bv*Hv];
__device__ __align__(16) float g_gi [Bv*3*Hv];
__device__ __align__(16) float g_gh [Bv*3*Hv];

// =================== FP16 tensor-core GEMM (m16n8k16) =======================
// C[M,N] = A[M,K] @ B[K,N] + bias (EPI=1: + exact GELU), fp32 accumulate.
// Inputs converted fp32->fp16 (RN) on the SMEM-store path; same 10-bit
// mantissa as TF32. Requires M%128==0, N%64==0, K%32==0.
// gridDim.z selects among 3 (B, bias, C) triples (QKV fusion).
//
// Block tile 128x64, 8 warps, warp tile 32x32, K-chunk 32 (2 k16 steps).
// SMEM (words): As[128][20] (32 halfs data + 8 pad), Bs[32][36] (64 halfs + 8 pad).
// A-frag reads bank-clean (20r+off); B via ldmatrix.x4.trans (rows 4k: clean).
// Structure per R4 (best known): prefetch -> compute -> sync -> store -> sync.

#define LDA_H 20
#define LDB_H 36

__device__ __forceinline__ uint32_t packh2(float lo, float hi) {
    __half2 h = __floats2half2_rn(lo, hi);   // lo -> .x (low half)
    return *reinterpret_cast<uint32_t*>(&h);
}

__device__ __forceinline__ void mma_f16(float c[4],
    uint32_t a0, uint32_t a1, uint32_t a2, uint32_t a3,
    uint32_t b0, uint32_t b1)
{
    asm volatile(
        "mma.sync.aligned.m16n8k16.row.col.f32.f16.f16.f32 "
        "{%0,%1,%2,%3}, {%4,%5,%6,%7}, {%8,%9}, {%0,%1,%2,%3};"
        : "+f"(c[0]), "+f"(c[1]), "+f"(c[2]), "+f"(c[3])
        : "r"(a0), "r"(a1), "r"(a2), "r"(a3), "r"(b0), "r"(b1));
}

__device__ __forceinline__ void ldsm4t(uint32_t& r0, uint32_t& r1,
                                       uint32_t& r2, uint32_t& r3, uint32_t addr)
{
    asm volatile("ldmatrix.sync.aligned.m8n8.x4.trans.shared.b16 {%0,%1,%2,%3}, [%4];"
        : "=r"(r0), "=r"(r1), "=r"(r2), "=r"(r3) : "r"(addr));
}

template<int EPI>
__global__ __launch_bounds__(256, 2) void gemm_f16_kernel(
    const float* __restrict__ A,
    const float* __restrict__ B0, const float* __restrict__ B1, const float* __restrict__ B2,
    const float* __restrict__ bias0, const float* __restrict__ bias1, const float* __restrict__ bias2,
    float* __restrict__ C0, float* __restrict__ C1, float* __restrict__ C2,
    int M, int N, int K)
{
    const int z = blockIdx.z;
    const float* B    = (z == 0) ? B0    : (z == 1) ? B1    : B2;
    const float* bias = (z == 0) ? bias0 : (z == 1) ? bias1 : bias2;
    float*       C    = (z == 0) ? C0    : (z == 1) ? C1    : C2;

    __shared__ uint32_t As[128 * LDA_H];   // 10 KB
    __shared__ uint32_t Bs[32 * LDB_H];    // 4.5 KB

    const int tid  = threadIdx.x;
    const int bm   = blockIdx.y * 128;
    const int bn   = blockIdx.x * 64;
    const int w    = tid >> 5, lane = tid & 31;
    const int warpM = w & 3;            // rows warpM*32
    const int warpN = w >> 2;           // cols warpN*32
    const int r    = lane >> 2;         // 0..7
    const int off  = lane & 3;          // 0..3

    // writer assignments (same global-coalesced pattern as R4)
    const int amrow = tid >> 3, ac = tid & 7;     // A rows amrow+32i, k-halfs 4ac..+3
    const int bkrow = tid >> 4, be = tid & 15;    // B k-rows bkrow+16i, n-halfs 4be..+3

    const float* Abase = A + (size_t)bm * K;
    const float* Bbase = B + bn;

    // A-frag reader base (word units)
    const int aBase = (warpM * 32 + r) * LDA_H + off;
    // B ldmatrix per-thread base byte address:
    //   row k = lane&15, col halfs = warpN*32 + ((lane>>4)&1)*8
    const uint32_t bs0 = (uint32_t)__cvta_generic_to_shared(Bs);
    const uint32_t ldsmBase = bs0 +
        (uint32_t)(((lane & 15) * LDB_H + warpN * 16 + ((lane >> 4) & 1) * 4) * 4);

    float4 ra[4], rb[2];

    // ---- prologue: load chunk 0, store ----
    #pragma unroll
    for (int i = 0; i < 4; i++)
        ra[i] = *(const float4*)(Abase + (size_t)(amrow + i * 32) * K + ac * 4);
    #pragma unroll
    for (int i = 0; i < 2; i++)
        rb[i] = *(const float4*)(Bbase + (size_t)(bkrow + i * 16) * N + be * 4);

    #pragma unroll
    for (int i = 0; i < 4; i++) {
        int m = amrow + i * 32;
        *(uint2*)&As[m * LDA_H + 2 * ac] =
            make_uint2(packh2(ra[i].x, ra[i].y), packh2(ra[i].z, ra[i].w));
    }
    #pragma unroll
    for (int i = 0; i < 2; i++) {
        int k = bkrow + i * 16;
        *(uint2*)&Bs[k * LDB_H + 2 * be] =
            make_uint2(packh2(rb[i].x, rb[i].y), packh2(rb[i].z, rb[i].w));
    }
    __syncthreads();

    float acc[2][4][4] = {};
    const int nk = K >> 5;

    #pragma unroll 1
    for (int ch = 0; ch < nk; ch++) {
        const bool has_next = (ch + 1) < nk;
        if (has_next) {
            int kk = (ch + 1) * 32;
            #pragma unroll
            for (int i = 0; i < 4; i++)
                ra[i] = *(const float4*)(Abase + (size_t)(amrow + i * 32) * K + kk + ac * 4);
            #pragma unroll
            for (int i = 0; i < 2; i++)
                rb[i] = *(const float4*)(Bbase + (size_t)(kk + bkrow + i * 16) * N + be * 4);
        }

        #pragma unroll
        for (int ks = 0; ks < 2; ks++) {
            // B fragments: two ldmatrix.x4.trans cover nt=0..3
            uint32_t bf[4][2];
            uint32_t baddr = ldsmBase + (uint32_t)(ks * 16 * LDB_H * 4);
            ldsm4t(bf[0][0], bf[0][1], bf[1][0], bf[1][1], baddr);
            ldsm4t(bf[2][0], bf[2][1], bf[3][0], bf[3][1], baddr + 32);

            // A fragments: 4 LDS.32 each, bank-clean, immediate offsets
            uint32_t af[2][4];
            #pragma unroll
            for (int mt = 0; mt < 2; mt++) {
                int b0i = aBase + mt * (16 * LDA_H) + ks * 8;
                af[mt][0] = As[b0i];
                af[mt][1] = As[b0i + 8 * LDA_H];
                af[mt][2] = As[b0i + 4];
                af[mt][3] = As[b0i + 8 * LDA_H + 4];
            }
            #pragma unroll
            for (int mt = 0; mt < 2; mt++)
                #pragma unroll
                for (int nt = 0; nt < 4; nt++)
                    mma_f16(acc[mt][nt], af[mt][0], af[mt][1], af[mt][2], af[mt][3],
                            bf[nt][0], bf[nt][1]);
        }
        __syncthreads();

        if (has_next) {
            #pragma unroll
            for (int i = 0; i < 4; i++) {
                int m = amrow + i * 32;
                *(uint2*)&As[m * LDA_H + 2 * ac] =
                    make_uint2(packh2(ra[i].x, ra[i].y), packh2(ra[i].z, ra[i].w));
            }
            #pragma unroll
            for (int i = 0; i < 2; i++) {
                int k = bkrow + i * 16;
                *(uint2*)&Bs[k * LDB_H + 2 * be] =
                    make_uint2(packh2(rb[i].x, rb[i].y), packh2(rb[i].z, rb[i].w));
            }
            __syncthreads();
        }
    }

    // epilogue (same fragment->C mapping as k8 path)
    #pragma unroll
    for (int mt = 0; mt < 2; mt++) {
        #pragma unroll
        for (int nt = 0; nt < 4; nt++) {
            int row0 = bm + warpM * 32 + mt * 16 + r;
            int col  = bn + warpN * 32 + nt * 8 + off * 2;
            float b0 = bias[col], b1 = bias[col + 1];
            float v00 = acc[mt][nt][0] + b0;
            float v01 = acc[mt][nt][1] + b1;
            float v10 = acc[mt][nt][2] + b0;
            float v11 = acc[mt][nt][3] + b1;
            if (EPI == 1) {
                v00 = 0.5f * v00 * (1.0f + erff(v00 * 0.70710678118654752f));
                v01 = 0.5f * v01 * (1.0f + erff(v01 * 0.70710678118654752f));
                v10 = 0.5f * v10 * (1.0f + erff(v10 * 0.70710678118654752f));
                v11 = 0.5f * v11 * (1.0f + erff(v11 * 0.70710678118654752f));
            }
            *(float2*)(C + (size_t)row0 * N + col)       = make_float2(v00, v01);
            *(float2*)(C + (size_t)(row0 + 8) * N + col) = make_float2(v10, v11);
        }
    }
}

static inline dim3 tc_grid(int M, int N, int z = 1) { return dim3(N / 64, M / 128, z); }

// =================== FFMA GEMM (small / decoder shapes) =====================
template<bool TRANSB, int EPI>
__global__ __launch_bounds__(256) void gemm_kernel(
    const float* __restrict__ A, const float* __restrict__ B,
    const float* __restrict__ bias, float* __restrict__ C,
    int M, int N, int K, int ldc)
{
    __shared__ float As[16][64];
    __shared__ float Bs[16][64];
    const int tid = threadIdx.x;
    const int bm = blockIdx.y * 64, bn = blockIdx.x * 64;
    const int ty = tid >> 4, tx = tid & 15;

    const int lm  = tid >> 2;
    const int lk4 = (tid & 3) * 4;
    const int lbk = tid >> 4;
    const int lbn4 = (tid & 15) * 4;

    float acc[4][4] = {};

    for (int kk = 0; kk < K; kk += 16) {
        float4 av = make_float4(0.f,0.f,0.f,0.f);
        if (bm + lm < M)
            av = *(const float4*)(A + (size_t)(bm + lm) * K + kk + lk4);
        As[lk4+0][lm] = av.x; As[lk4+1][lm] = av.y;
        As[lk4+2][lm] = av.z; As[lk4+3][lm] = av.w;

        if (TRANSB) {
            float4 bvv = make_float4(0.f,0.f,0.f,0.f);
            if (bn + lm < N)
                bvv = *(const float4*)(B + (size_t)(bn + lm) * K + kk + lk4);
            Bs[lk4+0][lm] = bvv.x; Bs[lk4+1][lm] = bvv.y;
            Bs[lk4+2][lm] = bvv.z; Bs[lk4+3][lm] = bvv.w;
        } else {
            float4 bvv = make_float4(0.f,0.f,0.f,0.f);
            if (bn + lbn4 < N)
                bvv = *(const float4*)(B + (size_t)(kk + lbk) * N + bn + lbn4);
            *(float4*)&Bs[lbk][lbn4] = bvv;
        }
        __syncthreads();

        #pragma unroll
        for (int k = 0; k < 16; k++) {
            float4 a = *(const float4*)&As[k][ty * 4];
            float4 b = *(const float4*)&Bs[k][tx * 4];
            acc[0][0] += a.x*b.x; acc[0][1] += a.x*b.y; acc[0][2] += a.x*b.z; acc[0][3] += a.x*b.w;
            acc[1][0] += a.y*b.x; acc[1][1] += a.y*b.y; acc[1][2] += a.y*b.z; acc[1][3] += a.y*b.w;
            acc[2][0] += a.z*b.x; acc[2][1] += a.z*b.y; acc[2][2] += a.z*b.z; acc[2][3] += a.z*b.w;
            acc[3][0] += a.w*b.x; acc[3][1] += a.w*b.y; acc[3][2] += a.w*b.z; acc[3][3] += a.w*b.w;
        }
        __syncthreads();
    }

    #pragma unroll
    for (int i = 0; i < 4; i++) {
        int row = bm + ty * 4 + i;
        if (row >= M) continue;
        #pragma unroll
        for (int j = 0; j < 4; j++) {
            int col = bn + tx * 4 + j;
            if (col >= N) continue;
            float vv = acc[i][j] + bias[col];
            if (EPI == 1) vv = 0.5f * vv * (1.0f + erff(vv * 0.70710678118654752f));
            C[(size_t)row * ldc + col] = vv;
        }
    }
}

static inline dim3 gemm_grid(int M, int N) { return dim3((N + 63) / 64, (M + 63) / 64); }

// ---------------- LayerNorm helpers ----------------------------------------
__device__ __forceinline__ float block_sum256(float v, float* red) {
    int tid = threadIdx.x;
    red[tid] = v;
    __syncthreads();
    #pragma unroll
    for (int s = 128; s > 0; s >>= 1) {
        if (tid < s) red[tid] += red[tid + s];
        __syncthreads();
    }
    float r = red[0];
    __syncthreads();
    return r;
}

__global__ __launch_bounds__(256) void embed_ln_kernel(
    const int* __restrict__ ids, const float* __restrict__ ew,
    const float* __restrict__ ep, const float* __restrict__ et,
    const float* __restrict__ g, const float* __restrict__ b,
    float* __restrict__ x)
{
    __shared__ float red[256];
    __shared__ float buf[Hv];
    int tok = blockIdx.x;
    int s = tok % Sv;
    int id = ids[tok];
    int tid = threadIdx.x;

    float sum = 0.f;
    #pragma unroll
    for (int i = 0; i < 3; i++) {
        int h = tid + i * 256;
        float v = ew[(size_t)id * Hv + h] + ep[(size_t)s * Hv + h] + et[h];
        buf[h] = v;
        sum += v;
    }
    sum = block_sum256(sum, red);
    float m = sum * (1.0f / Hv);
    float sq = 0.f;
    #pragma unroll
    for (int i = 0; i < 3; i++) {
        int h = tid + i * 256;
        float d = buf[h] - m;
        sq += d * d;
    }
    sq = block_sum256(sq, red);
    float rstd = rsqrtf(sq * (1.0f / Hv) + 1e-12f);
    #pragma unroll
    for (int i = 0; i < 3; i++) {
        int h = tid + i * 256;
        x[(size_t)tok * Hv + h] = (buf[h] - m) * rstd * g[h] + b[h];
    }
}

__global__ __launch_bounds__(256) void ln_residual_kernel(
    float* __restrict__ x, const float* __restrict__ delta,
    const float* __restrict__ g, const float* __restrict__ b)
{
    __shared__ float red[256];
    __shared__ float buf[Hv];
    int tok = blockIdx.x;
    int tid = threadIdx.x;
    size_t base = (size_t)tok * Hv;

    float sum = 0.f;
    #pragma unroll
    for (int i = 0; i < 3; i++) {
        int h = tid + i * 256;
        float v = x[base + h] + delta[base + h];
        buf[h] = v;
        sum += v;
    }
    sum = block_sum256(sum, red);
    float m = sum * (1.0f / Hv);
    float sq = 0.f;
    #pragma unroll
    for (int i = 0; i < 3; i++) {
        int h = tid + i * 256;
        float d = buf[h] - m;
        sq += d * d;
    }
    sq = block_sum256(sq, red);
    float rstd = rsqrtf(sq * (1.0f / Hv) + 1e-12f);
    #pragma unroll
    for (int i = 0; i < 3; i++) {
        int h = tid + i * 256;
        x[base + h] = (buf[h] - m) * rstd * g[h] + b[h];
    }
}

// ---------------- fused attention -------------------------------------------
#define QBLK 8
__global__ __launch_bounds__(256) void attn_kernel(
    const float* __restrict__ q, const float* __restrict__ k,
    const float* __restrict__ v, const int* __restrict__ mask,
    float* __restrict__ ctx)
{
    __shared__ float kv[Sv][65];
    __shared__ float qs[QBLK][64];
    __shared__ float p [QBLK][132];
    const int b = blockIdx.z, h = blockIdx.y, q0 = blockIdx.x * QBLK;
    const int tid = threadIdx.x;
    const int w = tid >> 5, lane = tid & 31;

    for (int idx = tid; idx < QBLK * 64; idx += 256) {
        int r = idx >> 6, c = idx & 63;
        qs[r][c] = q[(size_t)(b * Sv + q0 + r) * Hv + h * 64 + c];
    }
    for (int idx = tid; idx < Sv * 64; idx += 256) {
        int r = idx >> 6, c = idx & 63;
        kv[r][c] = k[(size_t)(b * Sv + r) * Hv + h * 64 + c];
    }
    __syncthreads();

    float sc[4];
    #pragma unroll
    for (int j = 0; j < 4; j++) {
        int key = lane + 32 * j;
        float s = 0.f;
        #pragma unroll
        for (int d = 0; d < 64; d++) s += qs[w][d] * kv[key][d];
        s *= 0.125f;
        s += (1.0f - (float)mask[b * Sv + key]) * -1e9f;
        sc[j] = s;
    }
    float mx = fmaxf(fmaxf(sc[0], sc[1]), fmaxf(sc[2], sc[3]));
    #pragma unroll
    for (int o = 16; o > 0; o >>= 1) mx = fmaxf(mx, __shfl_xor_sync(0xffffffffu, mx, o));
    float sum = 0.f;
    #pragma unroll
    for (int j = 0; j < 4; j++) { sc[j] = expf(sc[j] - mx); sum += sc[j]; }
    #pragma unroll
    for (int o = 16; o > 0; o >>= 1) sum += __shfl_xor_sync(0xffffffffu, sum, o);
    float inv = 1.0f / sum;
    #pragma unroll
    for (int j = 0; j < 4; j++) p[w][lane + 32 * j] = sc[j] * inv;
    __syncthreads();

    for (int idx = tid; idx < Sv * 64; idx += 256) {
        int r = idx >> 6, c = idx & 63;
        kv[r][c] = v[(size_t)(b * Sv + r) * Hv + h * 64 + c];
    }
    __syncthreads();

    float acc0 = 0.f, acc1 = 0.f;
    #pragma unroll 4
    for (int key = 0; key < Sv; key++) {
        float pw = p[w][key];
        acc0 += pw * kv[key][lane];
        acc1 += pw * kv[key][lane + 32];
    }
    size_t base = (size_t)(b * Sv + q0 + w) * Hv + h * 64;
    ctx[base + lane]      = acc0;
    ctx[base + lane + 32] = acc1;
}

// ---------------- decoder pieces ---------------------------------------------
__global__ __launch_bounds__(256) void copy_hidden_kernel(
    const float* __restrict__ x, float* __restrict__ h)
{
    int idx = blockIdx.x * 256 + threadIdx.x;
    int b = idx / Hv, j = idx % Hv;
    h[idx] = x[(size_t)(b * Sv + (Sv - 1)) * Hv + j];
}

__global__ __launch_bounds__(256) void dec_init_kernel(
    const float* __restrict__ ew, const float* __restrict__ ep,
    const float* __restrict__ et, const float* __restrict__ g,
    const float* __restrict__ b, float* __restrict__ xt)
{
    __shared__ float red[256];
    __shared__ float buf[Hv];
    int bb = blockIdx.x;
    int tid = threadIdx.x;
    float sum = 0.f;
    #pragma unroll
    for (int i = 0; i < 3; i++) {
        int h = tid + i * 256;
        float v = ew[(size_t)CLSv * Hv + h] + ep[h] + et[h];
        buf[h] = v;
        sum += v;
    }
    sum = block_sum256(sum, red);
    float m = sum * (1.0f / Hv);
    float sq = 0.f;
    #pragma unroll
    for (int i = 0; i < 3; i++) {
        int h = tid + i * 256;
        float d = buf[h] - m;
        sq += d * d;
    }
    sq = block_sum256(sq, red);
    float rstd = rsqrtf(sq * (1.0f / Hv) + 1e-12f);
    #pragma unroll
    for (int i = 0; i < 3; i++) {
        int h = tid + i * 256;
        xt[(size_t)bb * Hv + h] = (buf[h] - m) * rstd * g[h] + b[h];
    }
}

__device__ __forceinline__ float sigmf(float x) { return 1.0f / (1.0f + expf(-x)); }

__global__ __launch_bounds__(256) void gru_elem_kernel(
    const float* __restrict__ gi, const float* __restrict__ gh,
    float* __restrict__ h, float* __restrict__ xt)
{
    int idx = blockIdx.x * 256 + threadIdx.x;
    int b = idx / Hv, j = idx % Hv;
    size_t base = (size_t)b * 3 * Hv;
    float r = sigmf(gi[base + j]          + gh[base + j]);
    float z = sigmf(gi[base + Hv + j]     + gh[base + Hv + j]);
    float n = tanhf(gi[base + 2*Hv + j] + r * gh[base + 2*Hv + j]);
    float hn = (1.0f - z) * n + z * h[idx];
    h[idx]  = hn;
    xt[idx] = hn;
}

// ---------------- launch orchestration ----------------------------------------
extern "C" void kernel_launch(void* const* d_in, const int* in_sizes, int n_in,
                              void* d_out, int out_size)
{
    const int*   ids      = (const int*)  d_in[0];
    const int*   amask    = (const int*)  d_in[1];
    const float* emb_word = (const float*)d_in[2];
    const float* emb_pos  = (const float*)d_in[3];
    const float* emb_tok  = (const float*)d_in[4];
    const float* ln_emb_g = (const float*)d_in[5];
    const float* ln_emb_b = (const float*)d_in[6];
    const float* Wq       = (const float*)d_in[7];
    const float* Wk       = (const float*)d_in[8];
    const float* Wv       = (const float*)d_in[9];
    const float* Wo       = (const float*)d_in[10];
    const float* bq       = (const float*)d_in[11];
    const float* bk       = (const float*)d_in[12];
    const float* bv       = (const float*)d_in[13];
    const float* bo       = (const float*)d_in[14];
    const float* ln1_g    = (const float*)d_in[15];
    const float* ln1_b    = (const float*)d_in[16];
    const float* W1       = (const float*)d_in[17];
    const float* b1       = (const float*)d_in[18];
    const float* W2       = (const float*)d_in[19];
    const float* b2       = (const float*)d_in[20];
    const float* ln2_g    = (const float*)d_in[21];
    const float* ln2_b    = (const float*)d_in[22];
    const float* W_ih     = (const float*)d_in[23];
    const float* W_hh     = (const float*)d_in[24];
    const float* b_ih     = (const float*)d_in[25];
    const float* b_hh     = (const float*)d_in[26];
    const float* Wf       = (const float*)d_in[27];
    const float* bf       = (const float*)d_in[28];
    float* out = (float*)d_out;

    float *x, *q, *k, *v, *ctx, *t1, *ff, *xt, *h, *gi, *gh;
    cudaGetSymbolAddress((void**)&x,   g_x);
    cudaGetSymbolAddress((void**)&q,   g_q);
    cudaGetSymbolAddress((void**)&k,   g_k);
    cudaGetSymbolAddress((void**)&v,   g_v);
    cudaGetSymbolAddress((void**)&ctx, g_ctx);
    cudaGetSymbolAddress((void**)&t1,  g_t1);
    cudaGetSymbolAddress((void**)&ff,  g_ff);
    cudaGetSymbolAddress((void**)&xt,  g_xt);
    cudaGetSymbolAddress((void**)&h,   g_h);
    cudaGetSymbolAddress((void**)&gi,  g_gi);
    cudaGetSymbolAddress((void**)&gh,  g_gh);

    embed_ln_kernel<<<NTOK, 256>>>(ids, emb_word, emb_pos, emb_tok,
                                   ln_emb_g, ln_emb_b, x);

    for (int l = 0; l < Lv; l++) {
        const float* wq = Wq + (size_t)l * Hv * Hv;
        const float* wk = Wk + (size_t)l * Hv * Hv;
        const float* wv = Wv + (size_t)l * Hv * Hv;
        const float* wo = Wo + (size_t)l * Hv * Hv;
        const float* w1 = W1 + (size_t)l * Hv * FFv;
        const float* w2 = W2 + (size_t)l * FFv * Hv;

        // fused QKV: one launch, gridDim.z = 3
        gemm_f16_kernel<0><<<tc_grid(NTOK, Hv, 3), 256>>>(
            x, wq, wk, wv, bq + l*Hv, bk + l*Hv, bv + l*Hv, q, k, v,
            NTOK, Hv, Hv);

        attn_kernel<<<dim3(Sv/QBLK, NHv, Bv), 256>>>(q, k, v, amask, ctx);

        gemm_f16_kernel<0><<<tc_grid(NTOK, Hv), 256>>>(
            ctx, wo, wo, wo, bo + l*Hv, bo + l*Hv, bo + l*Hv, t1, t1, t1,
            NTOK, Hv, Hv);
        ln_residual_kernel<<<NTOK, 256>>>(x, t1, ln1_g + l*Hv, ln1_b + l*Hv);

        gemm_f16_kernel<1><<<tc_grid(NTOK, FFv), 256>>>(
            x, w1, w1, w1, b1 + l*FFv, b1 + l*FFv, b1 + l*FFv, ff, ff, ff,
            NTOK, FFv, Hv);
        gemm_f16_kernel<0><<<tc_grid(NTOK, Hv), 256>>>(
            ff, w2, w2, w2, b2 + l*Hv, b2 + l*Hv, b2 + l*Hv, t1, t1, t1,
            NTOK, Hv, FFv);
        ln_residual_kernel<<<NTOK, 256>>>(x, t1, ln2_g + l*Hv, ln2_b + l*Hv);
    }

    copy_hidden_kernel<<<(Bv*Hv)/256, 256>>>(x, h);
    dec_init_kernel<<<Bv, 256>>>(emb_word, emb_pos, emb_tok, ln_emb_g, ln_emb_b, xt);

    for (int t = 0; t < Tv; t++) {
        gemm_kernel<true,0><<<gemm_grid(Bv, 3*Hv), 256>>>(xt, W_ih, b_ih, gi, Bv, 3*Hv, Hv, 3*Hv);
        gemm_kernel<true,0><<<gemm_grid(Bv, 3*Hv), 256>>>(h,  W_hh, b_hh, gh, Bv, 3*Hv, Hv, 3*Hv);
        gru_elem_kernel<<<(Bv*Hv)/256, 256>>>(gi, gh, h, xt);
        gemm_kernel<false,0><<<gemm_grid(Bv, Cv), 256>>>(h, Wf, bf, out + t*Cv, Bv, Cv, Hv, Tv*Cv);
    }
}